// round 11
// baseline (speedup 1.0000x reference)
#include <cuda_runtime.h>
#include <cuda_fp16.h>
#include <cstdint>
#include <math.h>

// Shapes (fixed)
#define QL 1024
#define CL 2048
#define BATCH 16
#define DIM 1024

// GEMM tiling: 128x64 block tile, BK=32 (two k16 substeps), 256 threads
#define BM 128
#define BN 64
#define P32 20                       // padded row stride in b32 (16 data + 4 pad)
#define A_SUB (128 * P32)            // 2560 b32 per k16 A subtile
#define B_SUB (64 * P32)             // 1280 b32 per k16 B subtile
#define STG32 (2 * A_SUB + 2 * B_SUB)  // 7680 b32 = 30720 B per stage
#define NSTG 3
#define GEMM_SMEM (NSTG * STG32 * 4)   // 92160 B

// ---------------------------------------------------------------------------
// Split-plane scratch (fp16 hi/lo; lo pre-scaled by 2048)
// ---------------------------------------------------------------------------
__device__ __half g_qsph [(size_t)BATCH * QL * DIM];
__device__ __half g_qspl [(size_t)BATCH * QL * DIM];
__device__ __half g_csph [(size_t)BATCH * CL * DIM];
__device__ __half g_cspl [(size_t)BATCH * CL * DIM];
__device__ __half g_ctsph[(size_t)BATCH * DIM * CL];
__device__ __half g_ctspl[(size_t)BATCH * DIM * CL];
__device__ __half g_wisph[(size_t)DIM * DIM];
__device__ __half g_wispl[(size_t)DIM * DIM];
__device__ __half g_wosph[(size_t)DIM * 2 * DIM];
__device__ __half g_wospl[(size_t)DIM * 2 * DIM];
__device__ __half g_qbsph[(size_t)BATCH * QL * DIM];
__device__ __half g_qbspl[(size_t)BATCH * QL * DIM];
__device__ __half g_ssph [(size_t)BATCH * QL * CL];
__device__ __half g_sspl [(size_t)BATCH * QL * CL];
__device__ __half g_ctxsph[(size_t)BATCH * QL * DIM];
__device__ __half g_ctxspl[(size_t)BATCH * QL * DIM];

// ---------------------------------------------------------------------------
// helpers
// ---------------------------------------------------------------------------
__device__ __forceinline__ void cp16(uint32_t dst, const void* src) {
    asm volatile("cp.async.cg.shared.global [%0], [%1], 16;" :: "r"(dst), "l"(src));
}
__device__ __forceinline__ void cp_commit() { asm volatile("cp.async.commit_group;" ::: "memory"); }
__device__ __forceinline__ void cp_wait1()  { asm volatile("cp.async.wait_group 1;"  ::: "memory"); }

__device__ __forceinline__ void mma16(float* d, const uint32_t* a, const uint32_t* b) {
    asm volatile(
        "mma.sync.aligned.m16n8k16.row.col.f32.f16.f16.f32 "
        "{%0,%1,%2,%3}, {%4,%5,%6,%7}, {%8,%9}, {%0,%1,%2,%3};"
        : "+f"(d[0]), "+f"(d[1]), "+f"(d[2]), "+f"(d[3])
        : "r"(a[0]), "r"(a[1]), "r"(a[2]), "r"(a[3]), "r"(b[0]), "r"(b[1]));
}

// fp16 split: hi = rn_fp16(f); lo = rn_fp16((f - hi) * 2048)   (lo pre-scaled)
__device__ __forceinline__ void splith(float f, __half& h, __half& l) {
    h = __float2half_rn(f);
    l = __float2half_rn((f - __half2float(h)) * 2048.0f);
}

// ---------------------------------------------------------------------------
// C[m][n] = sum_k A[m][k]*B[n][k], fp32 result via fp16 2-plane split:
//   result = (Ah+Al/2048)(Bh+Bl/2048) ~= Ah*Bh + (Al*Bh + Ah*Bl)/2048
//   accH accumulates Ah*Bh; accL accumulates Al*Bh + Ah*Bl (pre-scaled planes).
// MODE 0: write split planes (Cv=hi half*, Cv2=lo half*)
// MODE 1: plain fp32 (Cv=float*)
// MODE 2: tanh fp32 (Cv=float*)
// A,B: fp16 hi/lo planes, K-contiguous rows. CONCAT: A=[A0|A1] split at Ksplit.
// ---------------------------------------------------------------------------
template<int MODE, bool CONCAT>
__global__ __launch_bounds__(256, 2)
void gemm_h3_kernel(const __half* __restrict__ Ah, const __half* __restrict__ Al,
                    const __half* __restrict__ A1h, const __half* __restrict__ A1l,
                    long Abs, long lda,
                    const __half* __restrict__ Bh, const __half* __restrict__ Bl,
                    long Bbs, long ldb,
                    void* __restrict__ Cv, void* __restrict__ Cv2,
                    long Cbs, long ldc,
                    int K, int Ksplit)
{
    extern __shared__ uint32_t smem32[];
    const uint32_t smem_addr = (uint32_t)__cvta_generic_to_shared(smem32);

    const int bi = blockIdx.z;
    const int m0 = blockIdx.y * BM;
    const int n0 = blockIdx.x * BN;
    const int tid  = threadIdx.x;
    const int lane = tid & 31;
    const int wid  = tid >> 5;
    const int wm = (wid & 3) * 32;     // warp m offset
    const int wn = (wid >> 2) * 32;    // warp n offset
    const int g  = lane >> 2;
    const int t  = lane & 3;

    const __half* A0h_b = Ah + (long)bi * Abs;
    const __half* A0l_b = Al + (long)bi * Abs;
    const __half* A1h_b = CONCAT ? (A1h + (long)bi * Abs) : A0h_b;
    const __half* A1l_b = CONCAT ? (A1l + (long)bi * Abs) : A0l_b;
    const __half* Bh_b  = Bh + (long)bi * Bbs;
    const __half* Bl_b  = Bl + (long)bi * Bbs;

    float accH[2][4][4], accL[2][4][4];
    #pragma unroll
    for (int i = 0; i < 2; i++)
        #pragma unroll
        for (int j = 0; j < 4; j++)
            #pragma unroll
            for (int r = 0; r < 4; r++) { accH[i][j][r] = 0.f; accL[i][j][r] = 0.f; }

    const int niter = K / 32;

    auto prefetch = [&](int it, int buf) {
        const int k0 = it * 32;
        const __half *pAh, *pAl; int ka;
        if (CONCAT && k0 >= Ksplit) { pAh = A1h_b; pAl = A1l_b; ka = k0 - Ksplit; }
        else                        { pAh = A0h_b; pAl = A0l_b; ka = k0; }
        const uint32_t sb32 = (uint32_t)buf * STG32;
        #pragma unroll
        for (int j = 0; j < 6; ++j) {
            const int task  = tid + j * 256;          // 0..1535
            const int rowt  = task >> 2;
            const int chunk = task & 3;               // 0,1: hi ; 2,3: lo
            const int plane = chunk >> 1;
            const int h16   = chunk & 1;              // +8 halfs
            uint32_t dst32; const __half* src;
            if (rowt < 256) {                         // A: 2 subk x 128 rows
                const int subk = rowt >> 7, row = rowt & 127;
                dst32 = sb32 + (uint32_t)subk * A_SUB + (uint32_t)row * P32
                        + (uint32_t)plane * 8 + (uint32_t)h16 * 4;
                src = (plane ? pAl : pAh) + (long)(m0 + row) * lda + ka + subk * 16 + h16 * 8;
            } else {                                  // B: 2 subk x 64 rows
                const int rt2 = rowt - 256;
                const int subk = rt2 >> 6, row = rt2 & 63;
                dst32 = sb32 + 2 * A_SUB + (uint32_t)subk * B_SUB + (uint32_t)row * P32
                        + (uint32_t)plane * 8 + (uint32_t)h16 * 4;
                src = (plane ? Bl_b : Bh_b) + (long)(n0 + row) * ldb + k0 + subk * 16 + h16 * 8;
            }
            cp16(smem_addr + dst32 * 4, src);
        }
    };

    prefetch(0, 0);
    cp_commit();
    if (niter > 1) prefetch(1, 1);
    cp_commit();

    for (int it = 0; it < niter; it++) {
        const int buf = it % NSTG;
        cp_wait1();
        __syncthreads();
        // writes buffer (it+2)%3 == (it-1)%3, fully consumed last iteration
        if (it + 2 < niter) prefetch(it + 2, (it + 2) % NSTG);
        cp_commit();

        const uint32_t sb32 = (uint32_t)buf * STG32;
        #pragma unroll
        for (int s = 0; s < 2; ++s) {                 // two k16 substeps
            const uint32_t* aS = smem32 + sb32 + (uint32_t)s * A_SUB;
            const uint32_t* bS = smem32 + sb32 + 2 * A_SUB + (uint32_t)s * B_SUB;

            uint32_t ah[2][4], al[2][4], bh[4][2], bl[4][2];
            #pragma unroll
            for (int i = 0; i < 2; i++) {
                const int r = wm + i * 16 + g;
                ah[i][0] = aS[r * P32 + t];         ah[i][1] = aS[(r + 8) * P32 + t];
                ah[i][2] = aS[r * P32 + t + 4];     ah[i][3] = aS[(r + 8) * P32 + t + 4];
                al[i][0] = aS[r * P32 + t + 8];     al[i][1] = aS[(r + 8) * P32 + t + 8];
                al[i][2] = aS[r * P32 + t + 12];    al[i][3] = aS[(r + 8) * P32 + t + 12];
            }
            #pragma unroll
            for (int j = 0; j < 4; j++) {
                const int n = wn + j * 8 + g;
                bh[j][0] = bS[n * P32 + t];     bh[j][1] = bS[n * P32 + t + 4];
                bl[j][0] = bS[n * P32 + t + 8]; bl[j][1] = bS[n * P32 + t + 12];
            }
            // term-outer: each group of 8 MMAs mutually independent
            #pragma unroll
            for (int i = 0; i < 2; i++)
                #pragma unroll
                for (int j = 0; j < 4; j++)
                    mma16(accH[i][j], ah[i], bh[j]);
            #pragma unroll
            for (int i = 0; i < 2; i++)
                #pragma unroll
                for (int j = 0; j < 4; j++)
                    mma16(accL[i][j], al[i], bh[j]);
            #pragma unroll
            for (int i = 0; i < 2; i++)
                #pragma unroll
                for (int j = 0; j < 4; j++)
                    mma16(accL[i][j], ah[i], bl[j]);
        }
        __syncthreads();
    }

    // epilogue: c0(g,2t) c1(g,2t+1) c2(g+8,2t) c3(g+8,2t+1)
    const float inv2048 = 1.0f / 2048.0f;
    #pragma unroll
    for (int i = 0; i < 2; i++) {
        const int r0 = m0 + wm + i * 16 + g;
        #pragma unroll
        for (int j = 0; j < 4; j++) {
            const int cc = n0 + wn + j * 8 + t * 2;
            float v0 = accH[i][j][0] + accL[i][j][0] * inv2048;
            float v1 = accH[i][j][1] + accL[i][j][1] * inv2048;
            float v2 = accH[i][j][2] + accL[i][j][2] * inv2048;
            float v3 = accH[i][j][3] + accL[i][j][3] * inv2048;
            if (MODE == 0) {
                __half* Ch = (__half*)Cv  + (long)bi * Cbs;
                __half* Cl = (__half*)Cv2 + (long)bi * Cbs;
                __half h0, l0, h1, l1;
                splith(v0, h0, l0); splith(v1, h1, l1);
                *(__half2*)&Ch[(long)r0 * ldc + cc] = __halves2half2(h0, h1);
                *(__half2*)&Cl[(long)r0 * ldc + cc] = __halves2half2(l0, l1);
                splith(v2, h0, l0); splith(v3, h1, l1);
                *(__half2*)&Ch[(long)(r0 + 8) * ldc + cc] = __halves2half2(h0, h1);
                *(__half2*)&Cl[(long)(r0 + 8) * ldc + cc] = __halves2half2(l0, l1);
            } else {
                float* Cp = (float*)Cv + (long)bi * Cbs;
                if (MODE == 2) { v0 = tanhf(v0); v1 = tanhf(v1); v2 = tanhf(v2); v3 = tanhf(v3); }
                *(float2*)&Cp[(long)r0 * ldc + cc]       = make_float2(v0, v1);
                *(float2*)&Cp[(long)(r0 + 8) * ldc + cc] = make_float2(v2, v3);
            }
        }
    }
}

// ---------------------------------------------------------------------------
// in[r0, r1, L] fp32 -> hi/lo fp16 planes at [(r1*R0 + r0)*L]  (dim swap+split)
// ---------------------------------------------------------------------------
__global__ __launch_bounds__(256)
void split_swap_h_kernel(const float* __restrict__ in,
                         __half* __restrict__ oh, __half* __restrict__ ol,
                         int R1, int L)
{
    const long r0 = blockIdx.x, r1 = blockIdx.y;
    const float* src = in + (r0 * R1 + r1) * (long)L;
    const long dbase = (r1 * gridDim.x + r0) * (long)L;
    for (int i = threadIdx.x * 2; i < L; i += blockDim.x * 2) {
        float2 v = *(const float2*)(src + i);
        __half h0, l0, h1, l1;
        splith(v.x, h0, l0); splith(v.y, h1, l1);
        *(__half2*)&oh[dbase + i] = __halves2half2(h0, h1);
        *(__half2*)&ol[dbase + i] = __halves2half2(l0, l1);
    }
}

// ---------------------------------------------------------------------------
// c[CL, B, DIM] -> ct hi/lo fp16 planes [B, DIM, CL]  (transpose + split)
// ---------------------------------------------------------------------------
__global__ __launch_bounds__(256)
void split_ct_h_kernel(const float* __restrict__ c,
                       __half* __restrict__ cth, __half* __restrict__ ctl)
{
    __shared__ float tile[32][33];
    const int b  = blockIdx.z;
    const int k0 = blockIdx.x * 32;
    const int d0 = blockIdx.y * 32;
    const int tx = threadIdx.x & 31;
    const int ty = threadIdx.x >> 5;

    #pragma unroll
    for (int r = 0; r < 32; r += 8)
        tile[ty + r][tx] = c[(long)(k0 + ty + r) * (BATCH * DIM) + (long)b * DIM + d0 + tx];
    __syncthreads();
    #pragma unroll
    for (int r = 0; r < 32; r += 8) {
        float f = tile[tx][ty + r];
        __half h, l;
        splith(f, h, l);
        long idx = ((long)b * DIM + d0 + ty + r) * CL + k0 + tx;
        cth[idx] = h;
        ctl[idx] = l;
    }
}

// ---------------------------------------------------------------------------
// softmax over rows of 2048: fp32 probs in place + hi/lo fp16 planes
// ---------------------------------------------------------------------------
__global__ __launch_bounds__(256)
void softmax_split_kernel(float* __restrict__ S,
                          __half* __restrict__ sh, __half* __restrict__ sl)
{
    const long rbase = (long)blockIdx.x * 2048;
    float* row = S + rbase;
    const int t = threadIdx.x;
    __shared__ float sred[8];

    float v[8];
    float mx = -3.402823466e38f;
    #pragma unroll
    for (int j = 0; j < 8; j++) {
        v[j] = row[t + j * 256];
        mx = fmaxf(mx, v[j]);
    }
    #pragma unroll
    for (int o = 16; o > 0; o >>= 1)
        mx = fmaxf(mx, __shfl_xor_sync(0xffffffffu, mx, o));
    if ((t & 31) == 0) sred[t >> 5] = mx;
    __syncthreads();
    mx = sred[0];
    #pragma unroll
    for (int w = 1; w < 8; w++) mx = fmaxf(mx, sred[w]);

    float s = 0.f;
    #pragma unroll
    for (int j = 0; j < 8; j++) {
        v[j] = expf(v[j] - mx);
        s += v[j];
    }
    #pragma unroll
    for (int o = 16; o > 0; o >>= 1)
        s += __shfl_xor_sync(0xffffffffu, s, o);
    __syncthreads();
    if ((t & 31) == 0) sred[t >> 5] = s;
    __syncthreads();
    s = 0.f;
    #pragma unroll
    for (int w = 0; w < 8; w++) s += sred[w];

    const float inv = 1.f / s;
    #pragma unroll
    for (int j = 0; j < 8; j++) {
        float p = v[j] * inv;
        __half h, l;
        splith(p, h, l);
        row[t + j * 256] = p;
        sh[rbase + t + j * 256] = h;
        sl[rbase + t + j * 256] = l;
    }
}

// ---------------------------------------------------------------------------
extern "C" void kernel_launch(void* const* d_in, const int* in_sizes, int n_in,
                              void* d_out, int out_size)
{
    (void)in_sizes; (void)n_in; (void)out_size;
    const float* q     = (const float*)d_in[0];   // [QL, B, DIM]
    const float* c     = (const float*)d_in[1];   // [CL, B, DIM]
    const float* W_in  = (const float*)d_in[2];   // [DIM, DIM]
    const float* W_out = (const float*)d_in[3];   // [DIM, 2*DIM]

    float* out   = (float*)d_out;                       // [QL, B, DIM]
    float* score = out + (size_t)QL * BATCH * DIM;      // [B, QL, CL]

    __half *qsph, *qspl, *csph, *cspl, *ctsph, *ctspl;
    __half *wisph, *wispl, *wosph, *wospl;
    __half *qbsph, *qbspl, *ssph, *sspl, *ctxsph, *ctxspl;
    cudaGetSymbolAddress((void**)&qsph,  g_qsph);  cudaGetSymbolAddress((void**)&qspl,  g_qspl);
    cudaGetSymbolAddress((void**)&csph,  g_csph);  cudaGetSymbolAddress((void**)&cspl,  g_cspl);
    cudaGetSymbolAddress((void**)&ctsph, g_ctsph); cudaGetSymbolAddress((void**)&ctspl, g_ctspl);
    cudaGetSymbolAddress((void**)&wisph, g_wisph); cudaGetSymbolAddress((void**)&wispl, g_wispl);
    cudaGetSymbolAddress((void**)&wosph, g_wosph); cudaGetSymbolAddress((void**)&wospl, g_wospl);
    cudaGetSymbolAddress((void**)&qbsph, g_qbsph); cudaGetSymbolAddress((void**)&qbspl, g_qbspl);
    cudaGetSymbolAddress((void**)&ssph,  g_ssph);  cudaGetSymbolAddress((void**)&sspl,  g_sspl);
    cudaGetSymbolAddress((void**)&ctxsph, g_ctxsph); cudaGetSymbolAddress((void**)&ctxspl, g_ctxspl);

    cudaFuncSetAttribute(gemm_h3_kernel<0, false>, cudaFuncAttributeMaxDynamicSharedMemorySize, GEMM_SMEM);
    cudaFuncSetAttribute(gemm_h3_kernel<1, false>, cudaFuncAttributeMaxDynamicSharedMemorySize, GEMM_SMEM);
    cudaFuncSetAttribute(gemm_h3_kernel<2, true >, cudaFuncAttributeMaxDynamicSharedMemorySize, GEMM_SMEM);

    const long sQB = (long)QL * DIM;       // per-batch strides
    const long sSC = (long)QL * CL;

    // -- pre-split passes (fp16 hi/lo planes) --
    split_swap_h_kernel<<<dim3(QL, BATCH), 256>>>(q, qsph, qspl, BATCH, DIM);
    split_swap_h_kernel<<<dim3(CL, BATCH), 256>>>(c, csph, cspl, BATCH, DIM);
    split_swap_h_kernel<<<dim3(DIM, 1), 256>>>(W_in,  wisph, wispl, 1, DIM);
    split_swap_h_kernel<<<dim3(DIM, 1), 256>>>(W_out, wosph, wospl, 1, 2 * DIM);
    split_ct_h_kernel<<<dim3(CL / 32, DIM / 32, BATCH), 256>>>(c, ctsph, ctspl);

    // -- stage 1: qb = q . W_in^T  (split fp16 out) --
    gemm_h3_kernel<0, false><<<dim3(DIM / BN, QL / BM, BATCH), 256, GEMM_SMEM>>>(
        qsph, qspl, nullptr, nullptr, sQB, DIM,
        wisph, wispl, 0, DIM,
        qbsph, qbspl, sQB, DIM,
        DIM, 0);

    // -- stage 2: score = qb . c^T  (fp32 into output region) --
    gemm_h3_kernel<1, false><<<dim3(CL / BN, QL / BM, BATCH), 256, GEMM_SMEM>>>(
        qbsph, qbspl, nullptr, nullptr, sQB, DIM,
        csph, cspl, (long)CL * DIM, DIM,
        score, nullptr, sSC, CL,
        DIM, 0);

    // -- stage 3: softmax (fp32 in place + split planes) --
    softmax_split_kernel<<<BATCH * QL, 256>>>(score, ssph, sspl);

    // -- stage 4: ctx = P . c  (split fp16 out) --
    gemm_h3_kernel<0, false><<<dim3(DIM / BN, QL / BM, BATCH), 256, GEMM_SMEM>>>(
        ssph, sspl, nullptr, nullptr, sSC, CL,
        ctsph, ctspl, (long)DIM * CL, CL,
        ctxsph, ctxspl, sQB, DIM,
        CL, 0);

    // -- stage 5: out = tanh([ctx|qb] . W_out^T)  (fp32 strided) --
    gemm_h3_kernel<2, true><<<dim3(DIM / BN, QL / BM, BATCH), 256, GEMM_SMEM>>>(
        ctxsph, ctxspl, qbsph, qbspl, sQB, DIM,
        wosph, wospl, 0, 2 * DIM,
        out, nullptr, DIM, (long)BATCH * DIM,
        2 * DIM, DIM);
}

// round 12
// speedup vs baseline: 1.2560x; 1.2560x over previous
#include <cuda_runtime.h>
#include <cuda_fp16.h>
#include <cstdint>
#include <math.h>

// Shapes (fixed)
#define QL 1024
#define CL 2048
#define BATCH 16
#define DIM 1024

// GEMM tiling: 128x64 block tile, BK=32 (two k16 substeps), 256 threads
#define BM 128
#define BN 64
#define P32 20                       // padded row stride in b32 (16 data + 4 pad)
#define A_SUB (128 * P32)            // 2560 b32 per k16 A subtile
#define B_SUB (64 * P32)             // 1280 b32 per k16 B subtile
#define STG32 (2 * A_SUB + 2 * B_SUB)  // 7680 b32 = 30720 B per stage
#define NSTG 3
#define GEMM_SMEM (NSTG * STG32 * 4)   // 92160 B

// ---------------------------------------------------------------------------
// Split-plane scratch (fp16 hi/lo; lo pre-scaled by 2048)
// ---------------------------------------------------------------------------
__device__ __half g_qsph [(size_t)BATCH * QL * DIM];
__device__ __half g_qspl [(size_t)BATCH * QL * DIM];
__device__ __half g_csph [(size_t)BATCH * CL * DIM];
__device__ __half g_cspl [(size_t)BATCH * CL * DIM];
__device__ __half g_ctsph[(size_t)BATCH * DIM * CL];   // ct hi (stage 4 B, single)
__device__ __half g_wisph[(size_t)DIM * DIM];
__device__ __half g_wispl[(size_t)DIM * DIM];
__device__ __half g_wosph[(size_t)DIM * 2 * DIM];      // W_out hi (stage 5 B, single)
__device__ __half g_qbsph[(size_t)BATCH * QL * DIM];
__device__ __half g_qbspl[(size_t)BATCH * QL * DIM];
__device__ __half g_ssph [(size_t)BATCH * QL * CL];    // P hi (stage 4 A, single)
__device__ __half g_ctxsph[(size_t)BATCH * QL * DIM];
__device__ __half g_ctxspl[(size_t)BATCH * QL * DIM];

// ---------------------------------------------------------------------------
// helpers
// ---------------------------------------------------------------------------
__device__ __forceinline__ void cp16(uint32_t dst, const void* src) {
    asm volatile("cp.async.cg.shared.global [%0], [%1], 16;" :: "r"(dst), "l"(src));
}
__device__ __forceinline__ void cp_commit() { asm volatile("cp.async.commit_group;" ::: "memory"); }
__device__ __forceinline__ void cp_wait1()  { asm volatile("cp.async.wait_group 1;"  ::: "memory"); }

__device__ __forceinline__ void mma16(float* d, const uint32_t* a, const uint32_t* b) {
    asm volatile(
        "mma.sync.aligned.m16n8k16.row.col.f32.f16.f16.f32 "
        "{%0,%1,%2,%3}, {%4,%5,%6,%7}, {%8,%9}, {%0,%1,%2,%3};"
        : "+f"(d[0]), "+f"(d[1]), "+f"(d[2]), "+f"(d[3])
        : "r"(a[0]), "r"(a[1]), "r"(a[2]), "r"(a[3]), "r"(b[0]), "r"(b[1]));
}

// fp16 split: hi = rn_fp16(f); lo = rn_fp16((f - hi) * 2048)   (lo pre-scaled)
__device__ __forceinline__ void splith(float f, __half& h, __half& l) {
    h = __float2half_rn(f);
    l = __float2half_rn((f - __half2float(h)) * 2048.0f);
}

// ---------------------------------------------------------------------------
// C[m][n] = sum_k A[m][k]*B[n][k], fp32 result via fp16 planes.
//   AT/BT in {1,2}: number of planes used per operand.
//   D = Ah*Bh  (+ Al*Bh if AT==2)  (+ Ah*Bl if BT==2); lo planes pre-scaled
//   by 2048, accumulated in accL, recombined as accH + accL/2048.
// MODE 0: write split planes (Cv=hi half*, Cv2=lo half*)
// MODE 1: plain fp32 (Cv=float*)
// MODE 2: tanh fp32 (Cv=float*)
// A,B: fp16 hi/lo planes, K-contiguous rows. CONCAT: A=[A0|A1] split at Ksplit.
// ---------------------------------------------------------------------------
template<int AT, int BT, int MODE, bool CONCAT>
__global__ __launch_bounds__(256, 2)
void gemm_h3_kernel(const __half* __restrict__ Ah, const __half* __restrict__ Al,
                    const __half* __restrict__ A1h, const __half* __restrict__ A1l,
                    long Abs, long lda,
                    const __half* __restrict__ Bh, const __half* __restrict__ Bl,
                    long Bbs, long ldb,
                    void* __restrict__ Cv, void* __restrict__ Cv2,
                    long Cbs, long ldc,
                    int K, int Ksplit)
{
    extern __shared__ uint32_t smem32[];
    const uint32_t smem_addr = (uint32_t)__cvta_generic_to_shared(smem32);

    const int bi = blockIdx.z;
    const int m0 = blockIdx.y * BM;
    const int n0 = blockIdx.x * BN;
    const int tid  = threadIdx.x;
    const int lane = tid & 31;
    const int wid  = tid >> 5;
    const int wm = (wid & 3) * 32;     // warp m offset
    const int wn = (wid >> 2) * 32;    // warp n offset
    const int g  = lane >> 2;
    const int t  = lane & 3;

    const bool useL = (AT == 2) || (BT == 2);

    const __half* A0h_b = Ah + (long)bi * Abs;
    const __half* A0l_b = (AT == 2) ? (Al + (long)bi * Abs) : A0h_b;
    const __half* A1h_b = CONCAT ? (A1h + (long)bi * Abs) : A0h_b;
    const __half* A1l_b = (CONCAT && AT == 2) ? (A1l + (long)bi * Abs) : A1h_b;
    const __half* Bh_b  = Bh + (long)bi * Bbs;
    const __half* Bl_b  = (BT == 2) ? (Bl + (long)bi * Bbs) : Bh_b;

    float accH[2][4][4], accL[2][4][4];
    #pragma unroll
    for (int i = 0; i < 2; i++)
        #pragma unroll
        for (int j = 0; j < 4; j++)
            #pragma unroll
            for (int r = 0; r < 4; r++) { accH[i][j][r] = 0.f; accL[i][j][r] = 0.f; }

    const int niter = K / 32;

    auto prefetch = [&](int it, int buf) {
        const int k0 = it * 32;
        const __half *pAh, *pAl; int ka;
        if (CONCAT && k0 >= Ksplit) { pAh = A1h_b; pAl = A1l_b; ka = k0 - Ksplit; }
        else                        { pAh = A0h_b; pAl = A0l_b; ka = k0; }
        const uint32_t sb32 = (uint32_t)buf * STG32;
        #pragma unroll
        for (int j = 0; j < 6; ++j) {
            const int task  = tid + j * 256;          // 0..1535
            const int rowt  = task >> 2;
            const int chunk = task & 3;               // 0,1: hi ; 2,3: lo
            const int plane = chunk >> 1;
            const int h16   = chunk & 1;              // +8 halfs
            uint32_t dst32; const __half* src;
            if (rowt < 256) {                         // A: 2 subk x 128 rows
                if (plane == 1 && AT == 1) continue;  // lo plane unused
                const int subk = rowt >> 7, row = rowt & 127;
                dst32 = sb32 + (uint32_t)subk * A_SUB + (uint32_t)row * P32
                        + (uint32_t)plane * 8 + (uint32_t)h16 * 4;
                src = (plane ? pAl : pAh) + (long)(m0 + row) * lda + ka + subk * 16 + h16 * 8;
            } else {                                  // B: 2 subk x 64 rows
                if (plane == 1 && BT == 1) continue;
                const int rt2 = rowt - 256;
                const int subk = rt2 >> 6, row = rt2 & 63;
                dst32 = sb32 + 2 * A_SUB + (uint32_t)subk * B_SUB + (uint32_t)row * P32
                        + (uint32_t)plane * 8 + (uint32_t)h16 * 4;
                src = (plane ? Bl_b : Bh_b) + (long)(n0 + row) * ldb + k0 + subk * 16 + h16 * 8;
            }
            cp16(smem_addr + dst32 * 4, src);
        }
    };

    prefetch(0, 0);
    cp_commit();
    if (niter > 1) prefetch(1, 1);
    cp_commit();

    for (int it = 0; it < niter; it++) {
        const int buf = it % NSTG;
        cp_wait1();
        __syncthreads();
        // writes buffer (it+2)%3 == (it-1)%3, fully consumed last iteration
        if (it + 2 < niter) prefetch(it + 2, (it + 2) % NSTG);
        cp_commit();

        const uint32_t sb32 = (uint32_t)buf * STG32;
        #pragma unroll
        for (int s = 0; s < 2; ++s) {                 // two k16 substeps
            const uint32_t* aS = smem32 + sb32 + (uint32_t)s * A_SUB;
            const uint32_t* bS = smem32 + sb32 + 2 * A_SUB + (uint32_t)s * B_SUB;

            uint32_t ah[2][4], al[2][4], bh[4][2], bl[4][2];
            #pragma unroll
            for (int i = 0; i < 2; i++) {
                const int r = wm + i * 16 + g;
                ah[i][0] = aS[r * P32 + t];         ah[i][1] = aS[(r + 8) * P32 + t];
                ah[i][2] = aS[r * P32 + t + 4];     ah[i][3] = aS[(r + 8) * P32 + t + 4];
                if (AT == 2) {
                    al[i][0] = aS[r * P32 + t + 8];     al[i][1] = aS[(r + 8) * P32 + t + 8];
                    al[i][2] = aS[r * P32 + t + 12];    al[i][3] = aS[(r + 8) * P32 + t + 12];
                }
            }
            #pragma unroll
            for (int j = 0; j < 4; j++) {
                const int n = wn + j * 8 + g;
                bh[j][0] = bS[n * P32 + t];     bh[j][1] = bS[n * P32 + t + 4];
                if (BT == 2) {
                    bl[j][0] = bS[n * P32 + t + 8]; bl[j][1] = bS[n * P32 + t + 12];
                }
            }
            // term-outer: each group of 8 MMAs mutually independent
            #pragma unroll
            for (int i = 0; i < 2; i++)
                #pragma unroll
                for (int j = 0; j < 4; j++)
                    mma16(accH[i][j], ah[i], bh[j]);
            if (AT == 2)
                #pragma unroll
                for (int i = 0; i < 2; i++)
                    #pragma unroll
                    for (int j = 0; j < 4; j++)
                        mma16(accL[i][j], al[i], bh[j]);
            if (BT == 2)
                #pragma unroll
                for (int i = 0; i < 2; i++)
                    #pragma unroll
                    for (int j = 0; j < 4; j++)
                        mma16(accL[i][j], ah[i], bl[j]);
        }
        __syncthreads();
    }

    // epilogue: c0(g,2t) c1(g,2t+1) c2(g+8,2t) c3(g+8,2t+1)
    const float inv2048 = 1.0f / 2048.0f;
    #pragma unroll
    for (int i = 0; i < 2; i++) {
        const int r0 = m0 + wm + i * 16 + g;
        #pragma unroll
        for (int j = 0; j < 4; j++) {
            const int cc = n0 + wn + j * 8 + t * 2;
            float v0 = accH[i][j][0], v1 = accH[i][j][1];
            float v2 = accH[i][j][2], v3 = accH[i][j][3];
            if (useL) {
                v0 += accL[i][j][0] * inv2048;
                v1 += accL[i][j][1] * inv2048;
                v2 += accL[i][j][2] * inv2048;
                v3 += accL[i][j][3] * inv2048;
            }
            if (MODE == 0) {
                __half* Ch = (__half*)Cv  + (long)bi * Cbs;
                __half* Cl = (__half*)Cv2 + (long)bi * Cbs;
                __half h0, l0, h1, l1;
                splith(v0, h0, l0); splith(v1, h1, l1);
                *(__half2*)&Ch[(long)r0 * ldc + cc] = __halves2half2(h0, h1);
                *(__half2*)&Cl[(long)r0 * ldc + cc] = __halves2half2(l0, l1);
                splith(v2, h0, l0); splith(v3, h1, l1);
                *(__half2*)&Ch[(long)(r0 + 8) * ldc + cc] = __halves2half2(h0, h1);
                *(__half2*)&Cl[(long)(r0 + 8) * ldc + cc] = __halves2half2(l0, l1);
            } else {
                float* Cp = (float*)Cv + (long)bi * Cbs;
                if (MODE == 2) { v0 = tanhf(v0); v1 = tanhf(v1); v2 = tanhf(v2); v3 = tanhf(v3); }
                *(float2*)&Cp[(long)r0 * ldc + cc]       = make_float2(v0, v1);
                *(float2*)&Cp[(long)(r0 + 8) * ldc + cc] = make_float2(v2, v3);
            }
        }
    }
}

// ---------------------------------------------------------------------------
// in[r0, r1, L] fp32 -> hi/lo fp16 planes at [(r1*R0 + r0)*L]  (dim swap+split)
// ---------------------------------------------------------------------------
__global__ __launch_bounds__(256)
void split_swap_h_kernel(const float* __restrict__ in,
                         __half* __restrict__ oh, __half* __restrict__ ol,
                         int R1, int L)
{
    const long r0 = blockIdx.x, r1 = blockIdx.y;
    const float* src = in + (r0 * R1 + r1) * (long)L;
    const long dbase = (r1 * gridDim.x + r0) * (long)L;
    for (int i = threadIdx.x * 2; i < L; i += blockDim.x * 2) {
        float2 v = *(const float2*)(src + i);
        __half h0, l0, h1, l1;
        splith(v.x, h0, l0); splith(v.y, h1, l1);
        *(__half2*)&oh[dbase + i] = __halves2half2(h0, h1);
        if (ol) *(__half2*)&ol[dbase + i] = __halves2half2(l0, l1);
    }
}

// ---------------------------------------------------------------------------
// c[CL, B, DIM] -> ct hi fp16 plane [B, DIM, CL]  (transpose, single plane)
// ---------------------------------------------------------------------------
__global__ __launch_bounds__(256)
void split_ct_h_kernel(const float* __restrict__ c, __half* __restrict__ cth)
{
    __shared__ float tile[32][33];
    const int b  = blockIdx.z;
    const int k0 = blockIdx.x * 32;
    const int d0 = blockIdx.y * 32;
    const int tx = threadIdx.x & 31;
    const int ty = threadIdx.x >> 5;

    #pragma unroll
    for (int r = 0; r < 32; r += 8)
        tile[ty + r][tx] = c[(long)(k0 + ty + r) * (BATCH * DIM) + (long)b * DIM + d0 + tx];
    __syncthreads();
    #pragma unroll
    for (int r = 0; r < 32; r += 8) {
        long idx = ((long)b * DIM + d0 + ty + r) * CL + k0 + tx;
        cth[idx] = __float2half_rn(tile[tx][ty + r]);
    }
}

// ---------------------------------------------------------------------------
// softmax over rows of 2048: fp32 probs in place + hi fp16 plane
// ---------------------------------------------------------------------------
__global__ __launch_bounds__(256)
void softmax_split_kernel(float* __restrict__ S, __half* __restrict__ sh)
{
    const long rbase = (long)blockIdx.x * 2048;
    float* row = S + rbase;
    const int t = threadIdx.x;
    __shared__ float sred[8];

    float v[8];
    float mx = -3.402823466e38f;
    #pragma unroll
    for (int j = 0; j < 8; j++) {
        v[j] = row[t + j * 256];
        mx = fmaxf(mx, v[j]);
    }
    #pragma unroll
    for (int o = 16; o > 0; o >>= 1)
        mx = fmaxf(mx, __shfl_xor_sync(0xffffffffu, mx, o));
    if ((t & 31) == 0) sred[t >> 5] = mx;
    __syncthreads();
    mx = sred[0];
    #pragma unroll
    for (int w = 1; w < 8; w++) mx = fmaxf(mx, sred[w]);

    float s = 0.f;
    #pragma unroll
    for (int j = 0; j < 8; j++) {
        v[j] = expf(v[j] - mx);
        s += v[j];
    }
    #pragma unroll
    for (int o = 16; o > 0; o >>= 1)
        s += __shfl_xor_sync(0xffffffffu, s, o);
    __syncthreads();
    if ((t & 31) == 0) sred[t >> 5] = s;
    __syncthreads();
    s = 0.f;
    #pragma unroll
    for (int w = 0; w < 8; w++) s += sred[w];

    const float inv = 1.f / s;
    #pragma unroll
    for (int j = 0; j < 8; j++) {
        float p = v[j] * inv;
        row[t + j * 256] = p;
        sh[rbase + t + j * 256] = __float2half_rn(p);
    }
}

// ---------------------------------------------------------------------------
extern "C" void kernel_launch(void* const* d_in, const int* in_sizes, int n_in,
                              void* d_out, int out_size)
{
    (void)in_sizes; (void)n_in; (void)out_size;
    const float* q     = (const float*)d_in[0];   // [QL, B, DIM]
    const float* c     = (const float*)d_in[1];   // [CL, B, DIM]
    const float* W_in  = (const float*)d_in[2];   // [DIM, DIM]
    const float* W_out = (const float*)d_in[3];   // [DIM, 2*DIM]

    float* out   = (float*)d_out;                       // [QL, B, DIM]
    float* score = out + (size_t)QL * BATCH * DIM;      // [B, QL, CL]

    __half *qsph, *qspl, *csph, *cspl, *ctsph;
    __half *wisph, *wispl, *wosph;
    __half *qbsph, *qbspl, *ssph, *ctxsph, *ctxspl;
    cudaGetSymbolAddress((void**)&qsph,  g_qsph);  cudaGetSymbolAddress((void**)&qspl,  g_qspl);
    cudaGetSymbolAddress((void**)&csph,  g_csph);  cudaGetSymbolAddress((void**)&cspl,  g_cspl);
    cudaGetSymbolAddress((void**)&ctsph, g_ctsph);
    cudaGetSymbolAddress((void**)&wisph, g_wisph); cudaGetSymbolAddress((void**)&wispl, g_wispl);
    cudaGetSymbolAddress((void**)&wosph, g_wosph);
    cudaGetSymbolAddress((void**)&qbsph, g_qbsph); cudaGetSymbolAddress((void**)&qbspl, g_qbspl);
    cudaGetSymbolAddress((void**)&ssph,  g_ssph);
    cudaGetSymbolAddress((void**)&ctxsph, g_ctxsph); cudaGetSymbolAddress((void**)&ctxspl, g_ctxspl);

    cudaFuncSetAttribute(gemm_h3_kernel<2, 2, 0, false>, cudaFuncAttributeMaxDynamicSharedMemorySize, GEMM_SMEM);
    cudaFuncSetAttribute(gemm_h3_kernel<2, 2, 1, false>, cudaFuncAttributeMaxDynamicSharedMemorySize, GEMM_SMEM);
    cudaFuncSetAttribute(gemm_h3_kernel<1, 1, 0, false>, cudaFuncAttributeMaxDynamicSharedMemorySize, GEMM_SMEM);
    cudaFuncSetAttribute(gemm_h3_kernel<2, 1, 2, true >, cudaFuncAttributeMaxDynamicSharedMemorySize, GEMM_SMEM);

    const long sQB = (long)QL * DIM;       // per-batch strides
    const long sSC = (long)QL * CL;

    // -- pre-split passes (fp16 planes) --
    split_swap_h_kernel<<<dim3(QL, BATCH), 256>>>(q, qsph, qspl, BATCH, DIM);
    split_swap_h_kernel<<<dim3(CL, BATCH), 256>>>(c, csph, cspl, BATCH, DIM);
    split_swap_h_kernel<<<dim3(DIM, 1), 256>>>(W_in,  wisph, wispl, 1, DIM);
    split_swap_h_kernel<<<dim3(DIM, 1), 256>>>(W_out, wosph, nullptr, 1, 2 * DIM);
    split_ct_h_kernel<<<dim3(CL / 32, DIM / 32, BATCH), 256>>>(c, ctsph);

    // -- stage 1: qb = q . W_in^T  (2x2 planes, split fp16 out) --
    gemm_h3_kernel<2, 2, 0, false><<<dim3(DIM / BN, QL / BM, BATCH), 256, GEMM_SMEM>>>(
        qsph, qspl, nullptr, nullptr, sQB, DIM,
        wisph, wispl, 0, DIM,
        qbsph, qbspl, sQB, DIM,
        DIM, 0);

    // -- stage 2: score = qb . c^T  (2x2 planes, fp32 into output region) --
    gemm_h3_kernel<2, 2, 1, false><<<dim3(CL / BN, QL / BM, BATCH), 256, GEMM_SMEM>>>(
        qbsph, qbspl, nullptr, nullptr, sQB, DIM,
        csph, cspl, (long)CL * DIM, DIM,
        score, nullptr, sSC, CL,
        DIM, 0);

    // -- stage 3: softmax (fp32 in place + hi plane) --
    softmax_split_kernel<<<BATCH * QL, 256>>>(score, ssph);

    // -- stage 4: ctx = P . c  (1x1 planes: single MMA term; split fp16 out) --
    gemm_h3_kernel<1, 1, 0, false><<<dim3(DIM / BN, QL / BM, BATCH), 256, GEMM_SMEM>>>(
        ssph, nullptr, nullptr, nullptr, sSC, CL,
        ctsph, nullptr, (long)DIM * CL, CL,
        ctxsph, ctxspl, sQB, DIM,
        CL, 0);

    // -- stage 5: out = tanh([ctx|qb] . W_out^T)  (2x1 planes, fp32 strided) --
    gemm_h3_kernel<2, 1, 2, true><<<dim3(DIM / BN, QL / BM, BATCH), 256, GEMM_SMEM>>>(
        ctxsph, ctxspl, qbsph, qbspl, sQB, DIM,
        wosph, nullptr, 0, 2 * DIM,
        out, nullptr, DIM, (long)BATCH * DIM,
        2 * DIM, DIM);
}

// round 13
// speedup vs baseline: 1.3262x; 1.0559x over previous
#include <cuda_runtime.h>
#include <cuda_fp16.h>
#include <cstdint>
#include <math.h>

// Shapes (fixed)
#define QL 1024
#define CL 2048
#define BATCH 16
#define DIM 1024

// GEMM tiling: 128x64 block tile, BK=32 (two k16 substeps), 256 threads
#define BM 128
#define BN 64
#define P32 20                       // padded row stride in b32 (16 data + 4 pad)
#define A_SUB (128 * P32)            // 2560 b32 per k16 A subtile
#define B_SUB (64 * P32)             // 1280 b32 per k16 B subtile
#define STG32 (2 * A_SUB + 2 * B_SUB)  // 7680 b32 = 30720 B per stage
#define NSTG 3
#define GEMM_SMEM (NSTG * STG32 * 4)   // 92160 B

// ---------------------------------------------------------------------------
// Split-plane scratch (fp16 hi/lo; lo pre-scaled by 2048)
// ---------------------------------------------------------------------------
__device__ __half g_qsph [(size_t)BATCH * QL * DIM];
__device__ __half g_qspl [(size_t)BATCH * QL * DIM];
__device__ __half g_csph [(size_t)BATCH * CL * DIM];
__device__ __half g_cspl [(size_t)BATCH * CL * DIM];
__device__ __half g_ctsph[(size_t)BATCH * DIM * CL];   // ct hi (stage 4 B, single)
__device__ __half g_wisph[(size_t)DIM * DIM];
__device__ __half g_wispl[(size_t)DIM * DIM];
__device__ __half g_wosph[(size_t)DIM * 2 * DIM];      // W_out hi (stage 5 B, single)
__device__ __half g_qbsph[(size_t)BATCH * QL * DIM];
__device__ __half g_qbspl[(size_t)BATCH * QL * DIM];
__device__ __half g_ssph [(size_t)BATCH * QL * CL];    // P hi (stage 4 A, single)
__device__ __half g_ctxsph[(size_t)BATCH * QL * DIM];
__device__ __half g_ctxspl[(size_t)BATCH * QL * DIM];

// ---------------------------------------------------------------------------
// helpers
// ---------------------------------------------------------------------------
__device__ __forceinline__ void cp16(uint32_t dst, const void* src) {
    asm volatile("cp.async.cg.shared.global [%0], [%1], 16;" :: "r"(dst), "l"(src));
}
__device__ __forceinline__ void cp_commit() { asm volatile("cp.async.commit_group;" ::: "memory"); }
__device__ __forceinline__ void cp_wait1()  { asm volatile("cp.async.wait_group 1;"  ::: "memory"); }

__device__ __forceinline__ void mma16(float* d, const uint32_t* a, const uint32_t* b) {
    asm volatile(
        "mma.sync.aligned.m16n8k16.row.col.f32.f16.f16.f32 "
        "{%0,%1,%2,%3}, {%4,%5,%6,%7}, {%8,%9}, {%0,%1,%2,%3};"
        : "+f"(d[0]), "+f"(d[1]), "+f"(d[2]), "+f"(d[3])
        : "r"(a[0]), "r"(a[1]), "r"(a[2]), "r"(a[3]), "r"(b[0]), "r"(b[1]));
}

__device__ __forceinline__ void ldmx4(uint32_t* r, uint32_t a) {
    asm volatile("ldmatrix.sync.aligned.m8n8.x4.shared.b16 {%0,%1,%2,%3}, [%4];"
        : "=r"(r[0]), "=r"(r[1]), "=r"(r[2]), "=r"(r[3]) : "r"(a));
}
__device__ __forceinline__ void ldmx2(uint32_t* r, uint32_t a) {
    asm volatile("ldmatrix.sync.aligned.m8n8.x2.shared.b16 {%0,%1}, [%2];"
        : "=r"(r[0]), "=r"(r[1]) : "r"(a));
}

// fp16 split: hi = rn_fp16(f); lo = rn_fp16((f - hi) * 2048)   (lo pre-scaled)
__device__ __forceinline__ void splith(float f, __half& h, __half& l) {
    h = __float2half_rn(f);
    l = __float2half_rn((f - __half2float(h)) * 2048.0f);
}

// ---------------------------------------------------------------------------
// C[m][n] = sum_k A[m][k]*B[n][k], fp32 result via fp16 planes.
//   AT/BT in {1,2}: number of planes used per operand.
//   D = Ah*Bh  (+ Al*Bh if AT==2)  (+ Ah*Bl if BT==2); lo planes pre-scaled
//   by 2048, accumulated in accL, recombined as accH + accL/2048.
// MODE 0: write split planes (Cv=hi half*, Cv2=lo half*)
// MODE 1: plain fp32 (Cv=float*)
// MODE 2: tanh fp32 (Cv=float*)
// Fragment loads via ldmatrix (x4 for A, x2 for B); P32=20 row padding is
// conflict-free under the 8-address ldmatrix phases (banks 20r mod 32).
// ---------------------------------------------------------------------------
template<int AT, int BT, int MODE, bool CONCAT>
__global__ __launch_bounds__(256, 2)
void gemm_h3_kernel(const __half* __restrict__ Ah, const __half* __restrict__ Al,
                    const __half* __restrict__ A1h, const __half* __restrict__ A1l,
                    long Abs, long lda,
                    const __half* __restrict__ Bh, const __half* __restrict__ Bl,
                    long Bbs, long ldb,
                    void* __restrict__ Cv, void* __restrict__ Cv2,
                    long Cbs, long ldc,
                    int K, int Ksplit)
{
    extern __shared__ uint32_t smem32[];
    const uint32_t smem_addr = (uint32_t)__cvta_generic_to_shared(smem32);

    const int bi = blockIdx.z;
    const int m0 = blockIdx.y * BM;
    const int n0 = blockIdx.x * BN;
    const int tid  = threadIdx.x;
    const int lane = tid & 31;
    const int wid  = tid >> 5;
    const int wm = (wid & 3) * 32;     // warp m offset
    const int wn = (wid >> 2) * 32;    // warp n offset
    const int g  = lane >> 2;
    const int t  = lane & 3;

    const bool useL = (AT == 2) || (BT == 2);

    const __half* A0h_b = Ah + (long)bi * Abs;
    const __half* A0l_b = (AT == 2) ? (Al + (long)bi * Abs) : A0h_b;
    const __half* A1h_b = CONCAT ? (A1h + (long)bi * Abs) : A0h_b;
    const __half* A1l_b = (CONCAT && AT == 2) ? (A1l + (long)bi * Abs) : A1h_b;
    const __half* Bh_b  = Bh + (long)bi * Bbs;
    const __half* Bl_b  = (BT == 2) ? (Bl + (long)bi * Bbs) : Bh_b;

    // ldmatrix per-lane byte offsets (within a k16 subtile region)
    // A x4: lanes 0-7 -> rows R+0..7 k0..7 ; 8-15 -> R+8..15 k0..7 ;
    //       16-23 -> R+0..7 k8..15 ; 24-31 -> R+8..15 k8..15
    const int laA = lane & 15, sgA = lane >> 4;
    uint32_t offA[2];
    #pragma unroll
    for (int i = 0; i < 2; i++)
        offA[i] = (uint32_t)(((wm + i * 16 + laA) * P32 + sgA * 4) * 4);
    // B x2: lanes 0-7 -> rows n0+0..7 k0..7 ; 8-15 -> rows n0+0..7 k8..15
    const int laB = lane & 7, sgB = (lane >> 3) & 1;
    uint32_t offB[4];
    #pragma unroll
    for (int j = 0; j < 4; j++)
        offB[j] = (uint32_t)(((wn + j * 8 + laB) * P32 + sgB * 4) * 4);

    float accH[2][4][4], accL[2][4][4];
    #pragma unroll
    for (int i = 0; i < 2; i++)
        #pragma unroll
        for (int j = 0; j < 4; j++)
            #pragma unroll
            for (int r = 0; r < 4; r++) { accH[i][j][r] = 0.f; accL[i][j][r] = 0.f; }

    const int niter = K / 32;

    auto prefetch = [&](int it, int buf) {
        const int k0 = it * 32;
        const __half *pAh, *pAl; int ka;
        if (CONCAT && k0 >= Ksplit) { pAh = A1h_b; pAl = A1l_b; ka = k0 - Ksplit; }
        else                        { pAh = A0h_b; pAl = A0l_b; ka = k0; }
        const uint32_t sb32 = (uint32_t)buf * STG32;
        #pragma unroll
        for (int j = 0; j < 6; ++j) {
            const int task  = tid + j * 256;          // 0..1535
            const int rowt  = task >> 2;
            const int chunk = task & 3;               // 0,1: hi ; 2,3: lo
            const int plane = chunk >> 1;
            const int h16   = chunk & 1;              // +8 halfs
            uint32_t dst32; const __half* src;
            if (rowt < 256) {                         // A: 2 subk x 128 rows
                if (plane == 1 && AT == 1) continue;  // lo plane unused
                const int subk = rowt >> 7, row = rowt & 127;
                dst32 = sb32 + (uint32_t)subk * A_SUB + (uint32_t)row * P32
                        + (uint32_t)plane * 8 + (uint32_t)h16 * 4;
                src = (plane ? pAl : pAh) + (long)(m0 + row) * lda + ka + subk * 16 + h16 * 8;
            } else {                                  // B: 2 subk x 64 rows
                if (plane == 1 && BT == 1) continue;
                const int rt2 = rowt - 256;
                const int subk = rt2 >> 6, row = rt2 & 63;
                dst32 = sb32 + 2 * A_SUB + (uint32_t)subk * B_SUB + (uint32_t)row * P32
                        + (uint32_t)plane * 8 + (uint32_t)h16 * 4;
                src = (plane ? Bl_b : Bh_b) + (long)(n0 + row) * ldb + k0 + subk * 16 + h16 * 8;
            }
            cp16(smem_addr + dst32 * 4, src);
        }
    };

    prefetch(0, 0);
    cp_commit();
    if (niter > 1) prefetch(1, 1);
    cp_commit();

    for (int it = 0; it < niter; it++) {
        const int buf = it % NSTG;
        cp_wait1();
        __syncthreads();
        // writes buffer (it+2)%3 == (it-1)%3, fully consumed last iteration
        if (it + 2 < niter) prefetch(it + 2, (it + 2) % NSTG);
        cp_commit();

        const uint32_t sb32 = (uint32_t)buf * STG32;
        #pragma unroll
        for (int s = 0; s < 2; ++s) {                 // two k16 substeps
            const uint32_t subA = smem_addr + (sb32 + (uint32_t)s * A_SUB) * 4;
            const uint32_t subB = smem_addr + (sb32 + 2 * A_SUB + (uint32_t)s * B_SUB) * 4;

            uint32_t ah[2][4], al[2][4], bh[4][2], bl[4][2];
            ldmx4(ah[0], subA + offA[0]);
            ldmx4(ah[1], subA + offA[1]);
            if (AT == 2) {
                ldmx4(al[0], subA + offA[0] + 32);    // lo plane at +8 b32
                ldmx4(al[1], subA + offA[1] + 32);
            }
            #pragma unroll
            for (int j = 0; j < 4; j++) {
                ldmx2(bh[j], subB + offB[j]);
                if (BT == 2) ldmx2(bl[j], subB + offB[j] + 32);
            }
            // term-outer: each group of 8 MMAs mutually independent
            #pragma unroll
            for (int i = 0; i < 2; i++)
                #pragma unroll
                for (int j = 0; j < 4; j++)
                    mma16(accH[i][j], ah[i], bh[j]);
            if (AT == 2)
                #pragma unroll
                for (int i = 0; i < 2; i++)
                    #pragma unroll
                    for (int j = 0; j < 4; j++)
                        mma16(accL[i][j], al[i], bh[j]);
            if (BT == 2)
                #pragma unroll
                for (int i = 0; i < 2; i++)
                    #pragma unroll
                    for (int j = 0; j < 4; j++)
                        mma16(accL[i][j], ah[i], bl[j]);
        }
        __syncthreads();
    }

    // epilogue: c0(g,2t) c1(g,2t+1) c2(g+8,2t) c3(g+8,2t+1)
    const float inv2048 = 1.0f / 2048.0f;
    #pragma unroll
    for (int i = 0; i < 2; i++) {
        const int r0 = m0 + wm + i * 16 + g;
        #pragma unroll
        for (int j = 0; j < 4; j++) {
            const int cc = n0 + wn + j * 8 + t * 2;
            float v0 = accH[i][j][0], v1 = accH[i][j][1];
            float v2 = accH[i][j][2], v3 = accH[i][j][3];
            if (useL) {
                v0 += accL[i][j][0] * inv2048;
                v1 += accL[i][j][1] * inv2048;
                v2 += accL[i][j][2] * inv2048;
                v3 += accL[i][j][3] * inv2048;
            }
            if (MODE == 0) {
                __half* Ch = (__half*)Cv  + (long)bi * Cbs;
                __half* Cl = (__half*)Cv2 + (long)bi * Cbs;
                __half h0, l0, h1, l1;
                splith(v0, h0, l0); splith(v1, h1, l1);
                *(__half2*)&Ch[(long)r0 * ldc + cc] = __halves2half2(h0, h1);
                *(__half2*)&Cl[(long)r0 * ldc + cc] = __halves2half2(l0, l1);
                splith(v2, h0, l0); splith(v3, h1, l1);
                *(__half2*)&Ch[(long)(r0 + 8) * ldc + cc] = __halves2half2(h0, h1);
                *(__half2*)&Cl[(long)(r0 + 8) * ldc + cc] = __halves2half2(l0, l1);
            } else {
                float* Cp = (float*)Cv + (long)bi * Cbs;
                if (MODE == 2) { v0 = tanhf(v0); v1 = tanhf(v1); v2 = tanhf(v2); v3 = tanhf(v3); }
                *(float2*)&Cp[(long)r0 * ldc + cc]       = make_float2(v0, v1);
                *(float2*)&Cp[(long)(r0 + 8) * ldc + cc] = make_float2(v2, v3);
            }
        }
    }
}

// ---------------------------------------------------------------------------
// in[r0, r1, L] fp32 -> hi/lo fp16 planes at [(r1*R0 + r0)*L]  (dim swap+split)
// ---------------------------------------------------------------------------
__global__ __launch_bounds__(256)
void split_swap_h_kernel(const float* __restrict__ in,
                         __half* __restrict__ oh, __half* __restrict__ ol,
                         int R1, int L)
{
    const long r0 = blockIdx.x, r1 = blockIdx.y;
    const float* src = in + (r0 * R1 + r1) * (long)L;
    const long dbase = (r1 * gridDim.x + r0) * (long)L;
    for (int i = threadIdx.x * 2; i < L; i += blockDim.x * 2) {
        float2 v = *(const float2*)(src + i);
        __half h0, l0, h1, l1;
        splith(v.x, h0, l0); splith(v.y, h1, l1);
        *(__half2*)&oh[dbase + i] = __halves2half2(h0, h1);
        if (ol) *(__half2*)&ol[dbase + i] = __halves2half2(l0, l1);
    }
}

// ---------------------------------------------------------------------------
// c[CL, B, DIM] -> ct hi fp16 plane [B, DIM, CL]  (transpose, single plane)
// ---------------------------------------------------------------------------
__global__ __launch_bounds__(256)
void split_ct_h_kernel(const float* __restrict__ c, __half* __restrict__ cth)
{
    __shared__ float tile[32][33];
    const int b  = blockIdx.z;
    const int k0 = blockIdx.x * 32;
    const int d0 = blockIdx.y * 32;
    const int tx = threadIdx.x & 31;
    const int ty = threadIdx.x >> 5;

    #pragma unroll
    for (int r = 0; r < 32; r += 8)
        tile[ty + r][tx] = c[(long)(k0 + ty + r) * (BATCH * DIM) + (long)b * DIM + d0 + tx];
    __syncthreads();
    #pragma unroll
    for (int r = 0; r < 32; r += 8) {
        long idx = ((long)b * DIM + d0 + ty + r) * CL + k0 + tx;
        cth[idx] = __float2half_rn(tile[tx][ty + r]);
    }
}

// ---------------------------------------------------------------------------
// softmax over rows of 2048: fp32 probs in place + hi fp16 plane
// ---------------------------------------------------------------------------
__global__ __launch_bounds__(256)
void softmax_split_kernel(float* __restrict__ S, __half* __restrict__ sh)
{
    const long rbase = (long)blockIdx.x * 2048;
    float* row = S + rbase;
    const int t = threadIdx.x;
    __shared__ float sred[8];

    float v[8];
    float mx = -3.402823466e38f;
    #pragma unroll
    for (int j = 0; j < 8; j++) {
        v[j] = row[t + j * 256];
        mx = fmaxf(mx, v[j]);
    }
    #pragma unroll
    for (int o = 16; o > 0; o >>= 1)
        mx = fmaxf(mx, __shfl_xor_sync(0xffffffffu, mx, o));
    if ((t & 31) == 0) sred[t >> 5] = mx;
    __syncthreads();
    mx = sred[0];
    #pragma unroll
    for (int w = 1; w < 8; w++) mx = fmaxf(mx, sred[w]);

    float s = 0.f;
    #pragma unroll
    for (int j = 0; j < 8; j++) {
        v[j] = expf(v[j] - mx);
        s += v[j];
    }
    #pragma unroll
    for (int o = 16; o > 0; o >>= 1)
        s += __shfl_xor_sync(0xffffffffu, s, o);
    __syncthreads();
    if ((t & 31) == 0) sred[t >> 5] = s;
    __syncthreads();
    s = 0.f;
    #pragma unroll
    for (int w = 0; w < 8; w++) s += sred[w];

    const float inv = 1.f / s;
    #pragma unroll
    for (int j = 0; j < 8; j++) {
        float p = v[j] * inv;
        row[t + j * 256] = p;
        sh[rbase + t + j * 256] = __float2half_rn(p);
    }
}

// ---------------------------------------------------------------------------
extern "C" void kernel_launch(void* const* d_in, const int* in_sizes, int n_in,
                              void* d_out, int out_size)
{
    (void)in_sizes; (void)n_in; (void)out_size;
    const float* q     = (const float*)d_in[0];   // [QL, B, DIM]
    const float* c     = (const float*)d_in[1];   // [CL, B, DIM]
    const float* W_in  = (const float*)d_in[2];   // [DIM, DIM]
    const float* W_out = (const float*)d_in[3];   // [DIM, 2*DIM]

    float* out   = (float*)d_out;                       // [QL, B, DIM]
    float* score = out + (size_t)QL * BATCH * DIM;      // [B, QL, CL]

    __half *qsph, *qspl, *csph, *cspl, *ctsph;
    __half *wisph, *wispl, *wosph;
    __half *qbsph, *qbspl, *ssph, *ctxsph, *ctxspl;
    cudaGetSymbolAddress((void**)&qsph,  g_qsph);  cudaGetSymbolAddress((void**)&qspl,  g_qspl);
    cudaGetSymbolAddress((void**)&csph,  g_csph);  cudaGetSymbolAddress((void**)&cspl,  g_cspl);
    cudaGetSymbolAddress((void**)&ctsph, g_ctsph);
    cudaGetSymbolAddress((void**)&wisph, g_wisph); cudaGetSymbolAddress((void**)&wispl, g_wispl);
    cudaGetSymbolAddress((void**)&wosph, g_wosph);
    cudaGetSymbolAddress((void**)&qbsph, g_qbsph); cudaGetSymbolAddress((void**)&qbspl, g_qbspl);
    cudaGetSymbolAddress((void**)&ssph,  g_ssph);
    cudaGetSymbolAddress((void**)&ctxsph, g_ctxsph); cudaGetSymbolAddress((void**)&ctxspl, g_ctxspl);

    cudaFuncSetAttribute(gemm_h3_kernel<2, 2, 0, false>, cudaFuncAttributeMaxDynamicSharedMemorySize, GEMM_SMEM);
    cudaFuncSetAttribute(gemm_h3_kernel<2, 2, 1, false>, cudaFuncAttributeMaxDynamicSharedMemorySize, GEMM_SMEM);
    cudaFuncSetAttribute(gemm_h3_kernel<1, 1, 0, false>, cudaFuncAttributeMaxDynamicSharedMemorySize, GEMM_SMEM);
    cudaFuncSetAttribute(gemm_h3_kernel<2, 1, 2, true >, cudaFuncAttributeMaxDynamicSharedMemorySize, GEMM_SMEM);

    const long sQB = (long)QL * DIM;       // per-batch strides
    const long sSC = (long)QL * CL;

    // -- pre-split passes (fp16 planes) --
    split_swap_h_kernel<<<dim3(QL, BATCH), 256>>>(q, qsph, qspl, BATCH, DIM);
    split_swap_h_kernel<<<dim3(CL, BATCH), 256>>>(c, csph, cspl, BATCH, DIM);
    split_swap_h_kernel<<<dim3(DIM, 1), 256>>>(W_in,  wisph, wispl, 1, DIM);
    split_swap_h_kernel<<<dim3(DIM, 1), 256>>>(W_out, wosph, nullptr, 1, 2 * DIM);
    split_ct_h_kernel<<<dim3(CL / 32, DIM / 32, BATCH), 256>>>(c, ctsph);

    // -- stage 1: qb = q . W_in^T  (2x2 planes, split fp16 out) --
    gemm_h3_kernel<2, 2, 0, false><<<dim3(DIM / BN, QL / BM, BATCH), 256, GEMM_SMEM>>>(
        qsph, qspl, nullptr, nullptr, sQB, DIM,
        wisph, wispl, 0, DIM,
        qbsph, qbspl, sQB, DIM,
        DIM, 0);

    // -- stage 2: score = qb . c^T  (2x2 planes, fp32 into output region) --
    gemm_h3_kernel<2, 2, 1, false><<<dim3(CL / BN, QL / BM, BATCH), 256, GEMM_SMEM>>>(
        qbsph, qbspl, nullptr, nullptr, sQB, DIM,
        csph, cspl, (long)CL * DIM, DIM,
        score, nullptr, sSC, CL,
        DIM, 0);

    // -- stage 3: softmax (fp32 in place + hi plane) --
    softmax_split_kernel<<<BATCH * QL, 256>>>(score, ssph);

    // -- stage 4: ctx = P . c  (1x1 planes: single MMA term; split fp16 out) --
    gemm_h3_kernel<1, 1, 0, false><<<dim3(DIM / BN, QL / BM, BATCH), 256, GEMM_SMEM>>>(
        ssph, nullptr, nullptr, nullptr, sSC, CL,
        ctsph, nullptr, (long)DIM * CL, CL,
        ctxsph, ctxspl, sQB, DIM,
        CL, 0);

    // -- stage 5: out = tanh([ctx|qb] . W_out^T)  (2x1 planes, fp32 strided) --
    gemm_h3_kernel<2, 1, 2, true><<<dim3(DIM / BN, QL / BM, BATCH), 256, GEMM_SMEM>>>(
        ctxsph, ctxspl, qbsph, qbspl, sQB, DIM,
        wosph, nullptr, 0, 2 * DIM,
        out, nullptr, DIM, (long)BATCH * DIM,
        2 * DIM, DIM);
}

// round 14
// speedup vs baseline: 1.5308x; 1.1543x over previous
#include <cuda_runtime.h>
#include <cuda_fp16.h>
#include <cstdint>
#include <math.h>

// Shapes (fixed)
#define QL 1024
#define CL 2048
#define BATCH 16
#define DIM 1024

// GEMM tiling: 128x64 block tile, BK=32 (two k16 substeps), 256 threads
#define BM 128
#define BN 64
#define P32 20                       // padded row stride in b32 (16 data + 4 pad)
#define A_SUB (128 * P32)            // 2560 b32 per k16 A subtile
#define B_SUB (64 * P32)             // 1280 b32 per k16 B subtile
#define STG32 (2 * A_SUB + 2 * B_SUB)  // 7680 b32 = 30720 B per stage
#define NSTG 3
#define GEMM_SMEM (NSTG * STG32 * 4)   // 92160 B

// ---------------------------------------------------------------------------
// Split-plane scratch (fp16 hi/lo; lo pre-scaled by 2048)
// ---------------------------------------------------------------------------
__device__ __half g_qsph [(size_t)BATCH * QL * DIM];
__device__ __half g_qspl [(size_t)BATCH * QL * DIM];
__device__ __half g_csph [(size_t)BATCH * CL * DIM];
__device__ __half g_cspl [(size_t)BATCH * CL * DIM];
__device__ __half g_ctsph[(size_t)BATCH * DIM * CL];   // ct hi (stage 4 B)
__device__ __half g_wisph[(size_t)DIM * DIM];
__device__ __half g_wispl[(size_t)DIM * DIM];
__device__ __half g_wosph[(size_t)DIM * 2 * DIM];      // W_out hi (stage 5 B)
__device__ __half g_qbsph[(size_t)BATCH * QL * DIM];
__device__ __half g_qbspl[(size_t)BATCH * QL * DIM];
__device__ __half g_ssph [(size_t)BATCH * QL * CL];    // P hi (stage 4 A)
__device__ __half g_ctxsph[(size_t)BATCH * QL * DIM];  // ctx hi (stage 5 A)

// ---------------------------------------------------------------------------
// helpers
// ---------------------------------------------------------------------------
__device__ __forceinline__ void cp16(uint32_t dst, const void* src) {
    asm volatile("cp.async.cg.shared.global [%0], [%1], 16;" :: "r"(dst), "l"(src));
}
__device__ __forceinline__ void cp_commit() { asm volatile("cp.async.commit_group;" ::: "memory"); }
__device__ __forceinline__ void cp_wait1()  { asm volatile("cp.async.wait_group 1;"  ::: "memory"); }

__device__ __forceinline__ void mma16(float* d, const uint32_t* a, const uint32_t* b) {
    asm volatile(
        "mma.sync.aligned.m16n8k16.row.col.f32.f16.f16.f32 "
        "{%0,%1,%2,%3}, {%4,%5,%6,%7}, {%8,%9}, {%0,%1,%2,%3};"
        : "+f"(d[0]), "+f"(d[1]), "+f"(d[2]), "+f"(d[3])
        : "r"(a[0]), "r"(a[1]), "r"(a[2]), "r"(a[3]), "r"(b[0]), "r"(b[1]));
}

__device__ __forceinline__ void ldmx4(uint32_t* r, uint32_t a) {
    asm volatile("ldmatrix.sync.aligned.m8n8.x4.shared.b16 {%0,%1,%2,%3}, [%4];"
        : "=r"(r[0]), "=r"(r[1]), "=r"(r[2]), "=r"(r[3]) : "r"(a));
}
__device__ __forceinline__ void ldmx2(uint32_t* r, uint32_t a) {
    asm volatile("ldmatrix.sync.aligned.m8n8.x2.shared.b16 {%0,%1}, [%2];"
        : "=r"(r[0]), "=r"(r[1]) : "r"(a));
}

// fp16 split: hi = rn_fp16(f); lo = rn_fp16((f - hi) * 2048)   (lo pre-scaled)
__device__ __forceinline__ void splith(float f, __half& h, __half& l) {
    h = __float2half_rn(f);
    l = __float2half_rn((f - __half2float(h)) * 2048.0f);
}

// ---------------------------------------------------------------------------
// C[m][n] = sum_k A[m][k]*B[n][k], fp32 result via fp16 planes.
//   AT/BT in {1,2}: number of planes used per operand.
//   D = Ah*Bh  (+ Al*Bh if AT==2)  (+ Ah*Bl if BT==2); lo planes pre-scaled
//   by 2048, accumulated in accL, recombined as accH + accL/2048.
// MODE 0: write split planes (Cv=hi half*, Cv2=lo half*)
// MODE 1: plain fp32 (Cv=float*)
// MODE 2: tanh fp32 (Cv=float*)
// MODE 3: hi fp16 plane only (Cv=half*)
// Fragment loads via ldmatrix (x4 for A, x2 for B); P32=20 row padding is
// conflict-free under the 8-address ldmatrix phases (banks 20r mod 32).
// ---------------------------------------------------------------------------
template<int AT, int BT, int MODE, bool CONCAT>
__global__ __launch_bounds__(256, 2)
void gemm_h3_kernel(const __half* __restrict__ Ah, const __half* __restrict__ Al,
                    const __half* __restrict__ A1h, const __half* __restrict__ A1l,
                    long Abs, long lda,
                    const __half* __restrict__ Bh, const __half* __restrict__ Bl,
                    long Bbs, long ldb,
                    void* __restrict__ Cv, void* __restrict__ Cv2,
                    long Cbs, long ldc,
                    int K, int Ksplit)
{
    extern __shared__ uint32_t smem32[];
    const uint32_t smem_addr = (uint32_t)__cvta_generic_to_shared(smem32);

    const int bi = blockIdx.z;
    const int m0 = blockIdx.y * BM;
    const int n0 = blockIdx.x * BN;
    const int tid  = threadIdx.x;
    const int lane = tid & 31;
    const int wid  = tid >> 5;
    const int wm = (wid & 3) * 32;     // warp m offset
    const int wn = (wid >> 2) * 32;    // warp n offset
    const int g  = lane >> 2;
    const int t  = lane & 3;

    const bool useL = (AT == 2) || (BT == 2);

    const __half* A0h_b = Ah + (long)bi * Abs;
    const __half* A0l_b = (AT == 2) ? (Al + (long)bi * Abs) : A0h_b;
    const __half* A1h_b = CONCAT ? (A1h + (long)bi * Abs) : A0h_b;
    const __half* A1l_b = (CONCAT && AT == 2) ? (A1l + (long)bi * Abs) : A1h_b;
    const __half* Bh_b  = Bh + (long)bi * Bbs;
    const __half* Bl_b  = (BT == 2) ? (Bl + (long)bi * Bbs) : Bh_b;

    // ldmatrix per-lane byte offsets (within a k16 subtile region)
    const int laA = lane & 15, sgA = lane >> 4;
    uint32_t offA[2];
    #pragma unroll
    for (int i = 0; i < 2; i++)
        offA[i] = (uint32_t)(((wm + i * 16 + laA) * P32 + sgA * 4) * 4);
    const int laB = lane & 7, sgB = (lane >> 3) & 1;
    uint32_t offB[4];
    #pragma unroll
    for (int j = 0; j < 4; j++)
        offB[j] = (uint32_t)(((wn + j * 8 + laB) * P32 + sgB * 4) * 4);

    float accH[2][4][4], accL[2][4][4];
    #pragma unroll
    for (int i = 0; i < 2; i++)
        #pragma unroll
        for (int j = 0; j < 4; j++)
            #pragma unroll
            for (int r = 0; r < 4; r++) { accH[i][j][r] = 0.f; accL[i][j][r] = 0.f; }

    const int niter = K / 32;

    auto prefetch = [&](int it, int buf) {
        const int k0 = it * 32;
        const __half *pAh, *pAl; int ka;
        if (CONCAT && k0 >= Ksplit) { pAh = A1h_b; pAl = A1l_b; ka = k0 - Ksplit; }
        else                        { pAh = A0h_b; pAl = A0l_b; ka = k0; }
        const uint32_t sb32 = (uint32_t)buf * STG32;
        #pragma unroll
        for (int j = 0; j < 6; ++j) {
            const int task  = tid + j * 256;          // 0..1535
            const int rowt  = task >> 2;
            const int chunk = task & 3;               // 0,1: hi ; 2,3: lo
            const int plane = chunk >> 1;
            const int h16   = chunk & 1;              // +8 halfs
            uint32_t dst32; const __half* src;
            if (rowt < 256) {                         // A: 2 subk x 128 rows
                if (plane == 1 && AT == 1) continue;  // lo plane unused
                const int subk = rowt >> 7, row = rowt & 127;
                dst32 = sb32 + (uint32_t)subk * A_SUB + (uint32_t)row * P32
                        + (uint32_t)plane * 8 + (uint32_t)h16 * 4;
                src = (plane ? pAl : pAh) + (long)(m0 + row) * lda + ka + subk * 16 + h16 * 8;
            } else {                                  // B: 2 subk x 64 rows
                if (plane == 1 && BT == 1) continue;
                const int rt2 = rowt - 256;
                const int subk = rt2 >> 6, row = rt2 & 63;
                dst32 = sb32 + 2 * A_SUB + (uint32_t)subk * B_SUB + (uint32_t)row * P32
                        + (uint32_t)plane * 8 + (uint32_t)h16 * 4;
                src = (plane ? Bl_b : Bh_b) + (long)(n0 + row) * ldb + k0 + subk * 16 + h16 * 8;
            }
            cp16(smem_addr + dst32 * 4, src);
        }
    };

    prefetch(0, 0);
    cp_commit();
    if (niter > 1) prefetch(1, 1);
    cp_commit();

    for (int it = 0; it < niter; it++) {
        const int buf = it % NSTG;
        cp_wait1();
        __syncthreads();
        // Single barrier per chunk: this barrier orders ALL warps' compute of
        // iteration it-1 before anyone prefetches into buffer (it+2)%3 ==
        // (it-1)%3. The next iteration's barrier likewise protects buffer
        // it%3 (computed below) from prefetch (it+3)%3 — no tail barrier
        // needed.
        if (it + 2 < niter) prefetch(it + 2, (it + 2) % NSTG);
        cp_commit();

        const uint32_t sb32 = (uint32_t)buf * STG32;
        #pragma unroll
        for (int s = 0; s < 2; ++s) {                 // two k16 substeps
            const uint32_t subA = smem_addr + (sb32 + (uint32_t)s * A_SUB) * 4;
            const uint32_t subB = smem_addr + (sb32 + 2 * A_SUB + (uint32_t)s * B_SUB) * 4;

            uint32_t ah[2][4], al[2][4], bh[4][2], bl[4][2];
            ldmx4(ah[0], subA + offA[0]);
            ldmx4(ah[1], subA + offA[1]);
            if (AT == 2) {
                ldmx4(al[0], subA + offA[0] + 32);    // lo plane at +8 b32
                ldmx4(al[1], subA + offA[1] + 32);
            }
            #pragma unroll
            for (int j = 0; j < 4; j++) {
                ldmx2(bh[j], subB + offB[j]);
                if (BT == 2) ldmx2(bl[j], subB + offB[j] + 32);
            }
            // term-outer: each group of 8 MMAs mutually independent
            #pragma unroll
            for (int i = 0; i < 2; i++)
                #pragma unroll
                for (int j = 0; j < 4; j++)
                    mma16(accH[i][j], ah[i], bh[j]);
            if (AT == 2)
                #pragma unroll
                for (int i = 0; i < 2; i++)
                    #pragma unroll
                    for (int j = 0; j < 4; j++)
                        mma16(accL[i][j], al[i], bh[j]);
            if (BT == 2)
                #pragma unroll
                for (int i = 0; i < 2; i++)
                    #pragma unroll
                    for (int j = 0; j < 4; j++)
                        mma16(accL[i][j], ah[i], bl[j]);
        }
    }

    // epilogue: c0(g,2t) c1(g,2t+1) c2(g+8,2t) c3(g+8,2t+1)
    const float inv2048 = 1.0f / 2048.0f;
    #pragma unroll
    for (int i = 0; i < 2; i++) {
        const int r0 = m0 + wm + i * 16 + g;
        #pragma unroll
        for (int j = 0; j < 4; j++) {
            const int cc = n0 + wn + j * 8 + t * 2;
            float v0 = accH[i][j][0], v1 = accH[i][j][1];
            float v2 = accH[i][j][2], v3 = accH[i][j][3];
            if (useL) {
                v0 += accL[i][j][0] * inv2048;
                v1 += accL[i][j][1] * inv2048;
                v2 += accL[i][j][2] * inv2048;
                v3 += accL[i][j][3] * inv2048;
            }
            if (MODE == 0) {
                __half* Ch = (__half*)Cv  + (long)bi * Cbs;
                __half* Cl = (__half*)Cv2 + (long)bi * Cbs;
                __half h0, l0, h1, l1;
                splith(v0, h0, l0); splith(v1, h1, l1);
                *(__half2*)&Ch[(long)r0 * ldc + cc] = __halves2half2(h0, h1);
                *(__half2*)&Cl[(long)r0 * ldc + cc] = __halves2half2(l0, l1);
                splith(v2, h0, l0); splith(v3, h1, l1);
                *(__half2*)&Ch[(long)(r0 + 8) * ldc + cc] = __halves2half2(h0, h1);
                *(__half2*)&Cl[(long)(r0 + 8) * ldc + cc] = __halves2half2(l0, l1);
            } else if (MODE == 3) {
                __half* Ch = (__half*)Cv + (long)bi * Cbs;
                *(__half2*)&Ch[(long)r0 * ldc + cc] =
                    __halves2half2(__float2half_rn(v0), __float2half_rn(v1));
                *(__half2*)&Ch[(long)(r0 + 8) * ldc + cc] =
                    __halves2half2(__float2half_rn(v2), __float2half_rn(v3));
            } else {
                float* Cp = (float*)Cv + (long)bi * Cbs;
                if (MODE == 2) { v0 = tanhf(v0); v1 = tanhf(v1); v2 = tanhf(v2); v3 = tanhf(v3); }
                *(float2*)&Cp[(long)r0 * ldc + cc]       = make_float2(v0, v1);
                *(float2*)&Cp[(long)(r0 + 8) * ldc + cc] = make_float2(v2, v3);
            }
        }
    }
}

// ---------------------------------------------------------------------------
// in[r0, r1, L] fp32 -> hi/lo fp16 planes at [(r1*R0 + r0)*L]  (dim swap+split)
// ---------------------------------------------------------------------------
__global__ __launch_bounds__(256)
void split_swap_h_kernel(const float* __restrict__ in,
                         __half* __restrict__ oh, __half* __restrict__ ol,
                         int R1, int L)
{
    const long r0 = blockIdx.x, r1 = blockIdx.y;
    const float* src = in + (r0 * R1 + r1) * (long)L;
    const long dbase = (r1 * gridDim.x + r0) * (long)L;
    for (int i = threadIdx.x * 2; i < L; i += blockDim.x * 2) {
        float2 v = *(const float2*)(src + i);
        __half h0, l0, h1, l1;
        splith(v.x, h0, l0); splith(v.y, h1, l1);
        *(__half2*)&oh[dbase + i] = __halves2half2(h0, h1);
        if (ol) *(__half2*)&ol[dbase + i] = __halves2half2(l0, l1);
    }
}

// ---------------------------------------------------------------------------
// Fused c pre-pass: one read of c[CL, B, DIM] produces
//   csph/cspl [B, CL, DIM]  (dim-swap + hi/lo split, stage 2 B)
//   ctsph     [B, DIM, CL]  (transpose hi plane, stage 4 B)
// ---------------------------------------------------------------------------
__global__ __launch_bounds__(256)
void split_c_fused_kernel(const float* __restrict__ c,
                          __half* __restrict__ csh, __half* __restrict__ csl,
                          __half* __restrict__ cth)
{
    __shared__ float tile[32][33];
    const int b  = blockIdx.z;
    const int k0 = blockIdx.x * 32;
    const int d0 = blockIdx.y * 32;
    const int tx = threadIdx.x & 31;
    const int ty = threadIdx.x >> 5;

    #pragma unroll
    for (int r = 0; r < 32; r += 8) {
        float f = c[(long)(k0 + ty + r) * (BATCH * DIM) + (long)b * DIM + d0 + tx];
        tile[ty + r][tx] = f;
        __half h, l;
        splith(f, h, l);
        long idx = ((long)b * CL + k0 + ty + r) * DIM + d0 + tx;   // [B, CL, DIM]
        csh[idx] = h;
        csl[idx] = l;
    }
    __syncthreads();
    #pragma unroll
    for (int r = 0; r < 32; r += 8) {
        long idx = ((long)b * DIM + d0 + ty + r) * CL + k0 + tx;   // [B, DIM, CL]
        cth[idx] = __float2half_rn(tile[tx][ty + r]);
    }
}

// ---------------------------------------------------------------------------
// softmax over rows of 2048: fp32 probs in place + hi fp16 plane (float4 I/O)
// ---------------------------------------------------------------------------
__global__ __launch_bounds__(256)
void softmax_split_kernel(float* __restrict__ S, __half* __restrict__ sh)
{
    const long rbase = (long)blockIdx.x * 2048;
    float* row = S + rbase;
    const int t = threadIdx.x;
    __shared__ float sred[8];

    float4 v[2];
    v[0] = *(const float4*)(row + t * 4);
    v[1] = *(const float4*)(row + 1024 + t * 4);
    float mx = fmaxf(fmaxf(v[0].x, v[0].y), fmaxf(v[0].z, v[0].w));
    mx = fmaxf(mx, fmaxf(fmaxf(v[1].x, v[1].y), fmaxf(v[1].z, v[1].w)));
    #pragma unroll
    for (int o = 16; o > 0; o >>= 1)
        mx = fmaxf(mx, __shfl_xor_sync(0xffffffffu, mx, o));
    if ((t & 31) == 0) sred[t >> 5] = mx;
    __syncthreads();
    mx = sred[0];
    #pragma unroll
    for (int w = 1; w < 8; w++) mx = fmaxf(mx, sred[w]);

    float s = 0.f;
    #pragma unroll
    for (int j = 0; j < 2; j++) {
        v[j].x = expf(v[j].x - mx); v[j].y = expf(v[j].y - mx);
        v[j].z = expf(v[j].z - mx); v[j].w = expf(v[j].w - mx);
        s += (v[j].x + v[j].y) + (v[j].z + v[j].w);
    }
    #pragma unroll
    for (int o = 16; o > 0; o >>= 1)
        s += __shfl_xor_sync(0xffffffffu, s, o);
    __syncthreads();
    if ((t & 31) == 0) sred[t >> 5] = s;
    __syncthreads();
    s = 0.f;
    #pragma unroll
    for (int w = 0; w < 8; w++) s += sred[w];

    const float inv = 1.f / s;
    #pragma unroll
    for (int j = 0; j < 2; j++) {
        v[j].x *= inv; v[j].y *= inv; v[j].z *= inv; v[j].w *= inv;
        *(float4*)(row + j * 1024 + t * 4) = v[j];
        __half2 h01 = __halves2half2(__float2half_rn(v[j].x), __float2half_rn(v[j].y));
        __half2 h23 = __halves2half2(__float2half_rn(v[j].z), __float2half_rn(v[j].w));
        *(__half2*)(sh + rbase + j * 1024 + t * 4)     = h01;
        *(__half2*)(sh + rbase + j * 1024 + t * 4 + 2) = h23;
    }
}

// ---------------------------------------------------------------------------
extern "C" void kernel_launch(void* const* d_in, const int* in_sizes, int n_in,
                              void* d_out, int out_size)
{
    (void)in_sizes; (void)n_in; (void)out_size;
    const float* q     = (const float*)d_in[0];   // [QL, B, DIM]
    const float* c     = (const float*)d_in[1];   // [CL, B, DIM]
    const float* W_in  = (const float*)d_in[2];   // [DIM, DIM]
    const float* W_out = (const float*)d_in[3];   // [DIM, 2*DIM]

    float* out   = (float*)d_out;                       // [QL, B, DIM]
    float* score = out + (size_t)QL * BATCH * DIM;      // [B, QL, CL]

    __half *qsph, *qspl, *csph, *cspl, *ctsph;
    __half *wisph, *wispl, *wosph;
    __half *qbsph, *qbspl, *ssph, *ctxsph;
    cudaGetSymbolAddress((void**)&qsph,  g_qsph);  cudaGetSymbolAddress((void**)&qspl,  g_qspl);
    cudaGetSymbolAddress((void**)&csph,  g_csph);  cudaGetSymbolAddress((void**)&cspl,  g_cspl);
    cudaGetSymbolAddress((void**)&ctsph, g_ctsph);
    cudaGetSymbolAddress((void**)&wisph, g_wisph); cudaGetSymbolAddress((void**)&wispl, g_wispl);
    cudaGetSymbolAddress((void**)&wosph, g_wosph);
    cudaGetSymbolAddress((void**)&qbsph, g_qbsph); cudaGetSymbolAddress((void**)&qbspl, g_qbspl);
    cudaGetSymbolAddress((void**)&ssph,  g_ssph);
    cudaGetSymbolAddress((void**)&ctxsph, g_ctxsph);

    cudaFuncSetAttribute(gemm_h3_kernel<2, 2, 0, false>, cudaFuncAttributeMaxDynamicSharedMemorySize, GEMM_SMEM);
    cudaFuncSetAttribute(gemm_h3_kernel<2, 2, 1, false>, cudaFuncAttributeMaxDynamicSharedMemorySize, GEMM_SMEM);
    cudaFuncSetAttribute(gemm_h3_kernel<1, 1, 3, false>, cudaFuncAttributeMaxDynamicSharedMemorySize, GEMM_SMEM);
    cudaFuncSetAttribute(gemm_h3_kernel<1, 1, 2, true >, cudaFuncAttributeMaxDynamicSharedMemorySize, GEMM_SMEM);

    const long sQB = (long)QL * DIM;       // per-batch strides
    const long sSC = (long)QL * CL;

    // -- pre-split passes (fp16 planes) --
    split_swap_h_kernel<<<dim3(QL, BATCH), 256>>>(q, qsph, qspl, BATCH, DIM);
    split_swap_h_kernel<<<dim3(DIM, 1), 256>>>(W_in,  wisph, wispl, 1, DIM);
    split_swap_h_kernel<<<dim3(DIM, 1), 256>>>(W_out, wosph, nullptr, 1, 2 * DIM);
    split_c_fused_kernel<<<dim3(CL / 32, DIM / 32, BATCH), 256>>>(c, csph, cspl, ctsph);

    // -- stage 1: qb = q . W_in^T  (2x2 planes, split fp16 out) --
    gemm_h3_kernel<2, 2, 0, false><<<dim3(DIM / BN, QL / BM, BATCH), 256, GEMM_SMEM>>>(
        qsph, qspl, nullptr, nullptr, sQB, DIM,
        wisph, wispl, 0, DIM,
        qbsph, qbspl, sQB, DIM,
        DIM, 0);

    // -- stage 2: score = qb . c^T  (2x2 planes, fp32 into output region) --
    gemm_h3_kernel<2, 2, 1, false><<<dim3(CL / BN, QL / BM, BATCH), 256, GEMM_SMEM>>>(
        qbsph, qbspl, nullptr, nullptr, sQB, DIM,
        csph, cspl, (long)CL * DIM, DIM,
        score, nullptr, sSC, CL,
        DIM, 0);

    // -- stage 3: softmax (fp32 in place + hi plane) --
    softmax_split_kernel<<<BATCH * QL, 256>>>(score, ssph);

    // -- stage 4: ctx = P . c  (1x1 planes; hi fp16 out only) --
    gemm_h3_kernel<1, 1, 3, false><<<dim3(DIM / BN, QL / BM, BATCH), 256, GEMM_SMEM>>>(
        ssph, nullptr, nullptr, nullptr, sSC, CL,
        ctsph, nullptr, (long)DIM * CL, CL,
        ctxsph, nullptr, sQB, DIM,
        CL, 0);

    // -- stage 5: out = tanh([ctx|qb] . W_out^T)  (1x1 planes, fp32 strided) --
    gemm_h3_kernel<1, 1, 2, true><<<dim3(DIM / BN, QL / BM, BATCH), 256, GEMM_SMEM>>>(
        ctxsph, nullptr, qbsph, nullptr, sQB, DIM,
        wosph, nullptr, 0, 2 * DIM,
        out, nullptr, DIM, (long)BATCH * DIM,
        2 * DIM, DIM);
}

// round 15
// speedup vs baseline: 1.5367x; 1.0039x over previous
#include <cuda_runtime.h>
#include <cuda_fp16.h>
#include <cstdint>
#include <math.h>

// Shapes (fixed)
#define QL 1024
#define CL 2048
#define BATCH 16
#define DIM 1024

// GEMM tiling: 128x64 block tile, BK=32 (two k16 substeps), 256 threads
#define BM 128
#define BN 64
#define P32 20                       // padded row stride in b32 (16 data + 4 pad)
#define A_SUB (128 * P32)            // 2560 b32 per k16 A subtile
#define B_SUB (64 * P32)             // 1280 b32 per k16 B subtile
#define STG32 (2 * A_SUB + 2 * B_SUB)  // 7680 b32 = 30720 B per stage
#define NSTG 3
#define GEMM_SMEM (NSTG * STG32 * 4)   // 92160 B

// ---------------------------------------------------------------------------
// Split-plane scratch (fp16 hi/lo; lo pre-scaled by 2048)
// ---------------------------------------------------------------------------
__device__ __half g_qsph [(size_t)BATCH * QL * DIM];
__device__ __half g_qspl [(size_t)BATCH * QL * DIM];
__device__ __half g_csph [(size_t)BATCH * CL * DIM];
__device__ __half g_cspl [(size_t)BATCH * CL * DIM];
__device__ __half g_ctsph[(size_t)BATCH * DIM * CL];   // ct hi (stage 4 B)
__device__ __half g_wisph[(size_t)DIM * DIM];
__device__ __half g_wispl[(size_t)DIM * DIM];
__device__ __half g_wosph[(size_t)DIM * 2 * DIM];      // W_out hi (stage 5 B)
__device__ __half g_qbsph[(size_t)BATCH * QL * DIM];
__device__ __half g_qbspl[(size_t)BATCH * QL * DIM];
__device__ __half g_ssph [(size_t)BATCH * QL * CL];    // P hi (stage 4 A)
__device__ __half g_ctxsph[(size_t)BATCH * QL * DIM];  // ctx hi (stage 5 A)

// ---------------------------------------------------------------------------
// helpers
// ---------------------------------------------------------------------------
__device__ __forceinline__ void cp16(uint32_t dst, const void* src) {
    asm volatile("cp.async.cg.shared.global [%0], [%1], 16;" :: "r"(dst), "l"(src));
}
__device__ __forceinline__ void cp_commit() { asm volatile("cp.async.commit_group;" ::: "memory"); }
__device__ __forceinline__ void cp_wait1()  { asm volatile("cp.async.wait_group 1;"  ::: "memory"); }

__device__ __forceinline__ void mma16(float* d, const uint32_t* a, const uint32_t* b) {
    asm volatile(
        "mma.sync.aligned.m16n8k16.row.col.f32.f16.f16.f32 "
        "{%0,%1,%2,%3}, {%4,%5,%6,%7}, {%8,%9}, {%0,%1,%2,%3};"
        : "+f"(d[0]), "+f"(d[1]), "+f"(d[2]), "+f"(d[3])
        : "r"(a[0]), "r"(a[1]), "r"(a[2]), "r"(a[3]), "r"(b[0]), "r"(b[1]));
}

__device__ __forceinline__ void ldmx4(uint32_t* r, uint32_t a) {
    asm volatile("ldmatrix.sync.aligned.m8n8.x4.shared.b16 {%0,%1,%2,%3}, [%4];"
        : "=r"(r[0]), "=r"(r[1]), "=r"(r[2]), "=r"(r[3]) : "r"(a));
}
__device__ __forceinline__ void ldmx2(uint32_t* r, uint32_t a) {
    asm volatile("ldmatrix.sync.aligned.m8n8.x2.shared.b16 {%0,%1}, [%2];"
        : "=r"(r[0]), "=r"(r[1]) : "r"(a));
}

// fp16 split: hi = rn_fp16(f); lo = rn_fp16((f - hi) * 2048)   (lo pre-scaled)
__device__ __forceinline__ void splith(float f, __half& h, __half& l) {
    h = __float2half_rn(f);
    l = __float2half_rn((f - __half2float(h)) * 2048.0f);
}

// fast tanh: 1 - 2/(1 + e^{2x}); saturates correctly (inf -> 1, 0 -> -1).
__device__ __forceinline__ float fast_tanh(float x) {
    return 1.0f - 2.0f / (1.0f + __expf(2.0f * x));
}

// ---------------------------------------------------------------------------
// C[m][n] = sum_k A[m][k]*B[n][k], fp32 result via fp16 planes.
//   AT/BT in {1,2}: number of planes used per operand.
//   D = Ah*Bh  (+ Al*Bh if AT==2)  (+ Ah*Bl if BT==2); lo planes pre-scaled
//   by 2048, accumulated in accL, recombined as accH + accL/2048.
// MODE 0: write split planes (Cv=hi half*, Cv2=lo half*)
// MODE 1: plain fp32 (Cv=float*)
// MODE 2: tanh fp32 (Cv=float*)
// MODE 3: hi fp16 plane only (Cv=half*)
// Fragment loads via ldmatrix (x4 for A, x2 for B); P32=20 row padding is
// conflict-free under the 8-address ldmatrix phases (banks 20r mod 32).
// ---------------------------------------------------------------------------
template<int AT, int BT, int MODE, bool CONCAT>
__global__ __launch_bounds__(256, 2)
void gemm_h3_kernel(const __half* __restrict__ Ah, const __half* __restrict__ Al,
                    const __half* __restrict__ A1h, const __half* __restrict__ A1l,
                    long Abs, long lda,
                    const __half* __restrict__ Bh, const __half* __restrict__ Bl,
                    long Bbs, long ldb,
                    void* __restrict__ Cv, void* __restrict__ Cv2,
                    long Cbs, long ldc,
                    int K, int Ksplit)
{
    extern __shared__ uint32_t smem32[];
    const uint32_t smem_addr = (uint32_t)__cvta_generic_to_shared(smem32);

    const int bi = blockIdx.z;
    const int m0 = blockIdx.y * BM;
    const int n0 = blockIdx.x * BN;
    const int tid  = threadIdx.x;
    const int lane = tid & 31;
    const int wid  = tid >> 5;
    const int wm = (wid & 3) * 32;     // warp m offset
    const int wn = (wid >> 2) * 32;    // warp n offset
    const int g  = lane >> 2;
    const int t  = lane & 3;

    const bool useL = (AT == 2) || (BT == 2);

    const __half* A0h_b = Ah + (long)bi * Abs;
    const __half* A0l_b = (AT == 2) ? (Al + (long)bi * Abs) : A0h_b;
    const __half* A1h_b = CONCAT ? (A1h + (long)bi * Abs) : A0h_b;
    const __half* A1l_b = (CONCAT && AT == 2) ? (A1l + (long)bi * Abs) : A1h_b;
    const __half* Bh_b  = Bh + (long)bi * Bbs;
    const __half* Bl_b  = (BT == 2) ? (Bl + (long)bi * Bbs) : Bh_b;

    // ldmatrix per-lane byte offsets (within a k16 subtile region)
    const int laA = lane & 15, sgA = lane >> 4;
    uint32_t offA[2];
    #pragma unroll
    for (int i = 0; i < 2; i++)
        offA[i] = (uint32_t)(((wm + i * 16 + laA) * P32 + sgA * 4) * 4);
    const int laB = lane & 7, sgB = (lane >> 3) & 1;
    uint32_t offB[4];
    #pragma unroll
    for (int j = 0; j < 4; j++)
        offB[j] = (uint32_t)(((wn + j * 8 + laB) * P32 + sgB * 4) * 4);

    float accH[2][4][4], accL[2][4][4];
    #pragma unroll
    for (int i = 0; i < 2; i++)
        #pragma unroll
        for (int j = 0; j < 4; j++)
            #pragma unroll
            for (int r = 0; r < 4; r++) { accH[i][j][r] = 0.f; accL[i][j][r] = 0.f; }

    const int niter = K / 32;

    auto prefetch = [&](int it, int buf) {
        const int k0 = it * 32;
        const __half *pAh, *pAl; int ka;
        if (CONCAT && k0 >= Ksplit) { pAh = A1h_b; pAl = A1l_b; ka = k0 - Ksplit; }
        else                        { pAh = A0h_b; pAl = A0l_b; ka = k0; }
        const uint32_t sb32 = (uint32_t)buf * STG32;
        #pragma unroll
        for (int j = 0; j < 6; ++j) {
            const int task  = tid + j * 256;          // 0..1535
            const int rowt  = task >> 2;
            const int chunk = task & 3;               // 0,1: hi ; 2,3: lo
            const int plane = chunk >> 1;
            const int h16   = chunk & 1;              // +8 halfs
            uint32_t dst32; const __half* src;
            if (rowt < 256) {                         // A: 2 subk x 128 rows
                if (plane == 1 && AT == 1) continue;  // lo plane unused
                const int subk = rowt >> 7, row = rowt & 127;
                dst32 = sb32 + (uint32_t)subk * A_SUB + (uint32_t)row * P32
                        + (uint32_t)plane * 8 + (uint32_t)h16 * 4;
                src = (plane ? pAl : pAh) + (long)(m0 + row) * lda + ka + subk * 16 + h16 * 8;
            } else {                                  // B: 2 subk x 64 rows
                if (plane == 1 && BT == 1) continue;
                const int rt2 = rowt - 256;
                const int subk = rt2 >> 6, row = rt2 & 63;
                dst32 = sb32 + 2 * A_SUB + (uint32_t)subk * B_SUB + (uint32_t)row * P32
                        + (uint32_t)plane * 8 + (uint32_t)h16 * 4;
                src = (plane ? Bl_b : Bh_b) + (long)(n0 + row) * ldb + k0 + subk * 16 + h16 * 8;
            }
            cp16(smem_addr + dst32 * 4, src);
        }
    };

    prefetch(0, 0);
    cp_commit();
    if (niter > 1) prefetch(1, 1);
    cp_commit();

    for (int it = 0; it < niter; it++) {
        const int buf = it % NSTG;
        cp_wait1();
        __syncthreads();
        // Single barrier per chunk: this barrier orders ALL warps' compute of
        // iteration it-1 before anyone prefetches into buffer (it+2)%3 ==
        // (it-1)%3. The next iteration's barrier likewise protects buffer
        // it%3 from prefetch (it+3)%3 — no tail barrier needed.
        if (it + 2 < niter) prefetch(it + 2, (it + 2) % NSTG);
        cp_commit();

        const uint32_t sb32 = (uint32_t)buf * STG32;
        #pragma unroll
        for (int s = 0; s < 2; ++s) {                 // two k16 substeps
            const uint32_t subA = smem_addr + (sb32 + (uint32_t)s * A_SUB) * 4;
            const uint32_t subB = smem_addr + (sb32 + 2 * A_SUB + (uint32_t)s * B_SUB) * 4;

            uint32_t ah[2][4], al[2][4], bh[4][2], bl[4][2];
            ldmx4(ah[0], subA + offA[0]);
            ldmx4(ah[1], subA + offA[1]);
            if (AT == 2) {
                ldmx4(al[0], subA + offA[0] + 32);    // lo plane at +8 b32
                ldmx4(al[1], subA + offA[1] + 32);
            }
            #pragma unroll
            for (int j = 0; j < 4; j++) {
                ldmx2(bh[j], subB + offB[j]);
                if (BT == 2) ldmx2(bl[j], subB + offB[j] + 32);
            }
            // term-outer: each group of 8 MMAs mutually independent
            #pragma unroll
            for (int i = 0; i < 2; i++)
                #pragma unroll
                for (int j = 0; j < 4; j++)
                    mma16(accH[i][j], ah[i], bh[j]);
            if (AT == 2)
                #pragma unroll
                for (int i = 0; i < 2; i++)
                    #pragma unroll
                    for (int j = 0; j < 4; j++)
                        mma16(accL[i][j], al[i], bh[j]);
            if (BT == 2)
                #pragma unroll
                for (int i = 0; i < 2; i++)
                    #pragma unroll
                    for (int j = 0; j < 4; j++)
                        mma16(accL[i][j], ah[i], bl[j]);
        }
    }

    // epilogue: c0(g,2t) c1(g,2t+1) c2(g+8,2t) c3(g+8,2t+1)
    const float inv2048 = 1.0f / 2048.0f;
    #pragma unroll
    for (int i = 0; i < 2; i++) {
        const int r0 = m0 + wm + i * 16 + g;
        #pragma unroll
        for (int j = 0; j < 4; j++) {
            const int cc = n0 + wn + j * 8 + t * 2;
            float v0 = accH[i][j][0], v1 = accH[i][j][1];
            float v2 = accH[i][j][2], v3 = accH[i][j][3];
            if (useL) {
                v0 += accL[i][j][0] * inv2048;
                v1 += accL[i][j][1] * inv2048;
                v2 += accL[i][j][2] * inv2048;
                v3 += accL[i][j][3] * inv2048;
            }
            if (MODE == 0) {
                __half* Ch = (__half*)Cv  + (long)bi * Cbs;
                __half* Cl = (__half*)Cv2 + (long)bi * Cbs;
                __half h0, l0, h1, l1;
                splith(v0, h0, l0); splith(v1, h1, l1);
                *(__half2*)&Ch[(long)r0 * ldc + cc] = __halves2half2(h0, h1);
                *(__half2*)&Cl[(long)r0 * ldc + cc] = __halves2half2(l0, l1);
                splith(v2, h0, l0); splith(v3, h1, l1);
                *(__half2*)&Ch[(long)(r0 + 8) * ldc + cc] = __halves2half2(h0, h1);
                *(__half2*)&Cl[(long)(r0 + 8) * ldc + cc] = __halves2half2(l0, l1);
            } else if (MODE == 3) {
                __half* Ch = (__half*)Cv + (long)bi * Cbs;
                *(__half2*)&Ch[(long)r0 * ldc + cc] =
                    __halves2half2(__float2half_rn(v0), __float2half_rn(v1));
                *(__half2*)&Ch[(long)(r0 + 8) * ldc + cc] =
                    __halves2half2(__float2half_rn(v2), __float2half_rn(v3));
            } else {
                float* Cp = (float*)Cv + (long)bi * Cbs;
                if (MODE == 2) {
                    v0 = fast_tanh(v0); v1 = fast_tanh(v1);
                    v2 = fast_tanh(v2); v3 = fast_tanh(v3);
                }
                *(float2*)&Cp[(long)r0 * ldc + cc]       = make_float2(v0, v1);
                *(float2*)&Cp[(long)(r0 + 8) * ldc + cc] = make_float2(v2, v3);
            }
        }
    }
}

// ---------------------------------------------------------------------------
// in[r0, r1, L] fp32 -> hi/lo fp16 planes at [(r1*R0 + r0)*L]  (dim swap+split)
// float4 I/O (L multiple of 4 x blockDim coverage).
// ---------------------------------------------------------------------------
__global__ __launch_bounds__(256)
void split_swap_h_kernel(const float* __restrict__ in,
                         __half* __restrict__ oh, __half* __restrict__ ol,
                         int R1, int L)
{
    const long r0 = blockIdx.x, r1 = blockIdx.y;
    const float* src = in + (r0 * R1 + r1) * (long)L;
    const long dbase = (r1 * gridDim.x + r0) * (long)L;
    for (int i = threadIdx.x * 4; i < L; i += blockDim.x * 4) {
        float4 v = *(const float4*)(src + i);
        __half h0, l0, h1, l1, h2, l2, h3, l3;
        splith(v.x, h0, l0); splith(v.y, h1, l1);
        splith(v.z, h2, l2); splith(v.w, h3, l3);
        *(__half2*)&oh[dbase + i]     = __halves2half2(h0, h1);
        *(__half2*)&oh[dbase + i + 2] = __halves2half2(h2, h3);
        if (ol) {
            *(__half2*)&ol[dbase + i]     = __halves2half2(l0, l1);
            *(__half2*)&ol[dbase + i + 2] = __halves2half2(l2, l3);
        }
    }
}

// ---------------------------------------------------------------------------
// Fused c pre-pass: one read of c[CL, B, DIM] produces
//   csph/cspl [B, CL, DIM]  (dim-swap + hi/lo split, stage 2 B)
//   ctsph     [B, DIM, CL]  (transpose hi plane, stage 4 B)
// ---------------------------------------------------------------------------
__global__ __launch_bounds__(256)
void split_c_fused_kernel(const float* __restrict__ c,
                          __half* __restrict__ csh, __half* __restrict__ csl,
                          __half* __restrict__ cth)
{
    __shared__ float tile[32][33];
    const int b  = blockIdx.z;
    const int k0 = blockIdx.x * 32;
    const int d0 = blockIdx.y * 32;
    const int tx = threadIdx.x & 31;
    const int ty = threadIdx.x >> 5;

    #pragma unroll
    for (int r = 0; r < 32; r += 8) {
        float f = c[(long)(k0 + ty + r) * (BATCH * DIM) + (long)b * DIM + d0 + tx];
        tile[ty + r][tx] = f;
        __half h, l;
        splith(f, h, l);
        long idx = ((long)b * CL + k0 + ty + r) * DIM + d0 + tx;   // [B, CL, DIM]
        csh[idx] = h;
        csl[idx] = l;
    }
    __syncthreads();
    #pragma unroll
    for (int r = 0; r < 32; r += 8) {
        long idx = ((long)b * DIM + d0 + ty + r) * CL + k0 + tx;   // [B, DIM, CL]
        cth[idx] = __float2half_rn(tile[tx][ty + r]);
    }
}

// ---------------------------------------------------------------------------
// softmax over rows of 2048: fp32 probs in place + hi fp16 plane (float4 I/O)
// ---------------------------------------------------------------------------
__global__ __launch_bounds__(256)
void softmax_split_kernel(float* __restrict__ S, __half* __restrict__ sh)
{
    const long rbase = (long)blockIdx.x * 2048;
    float* row = S + rbase;
    const int t = threadIdx.x;
    __shared__ float sred[8];

    float4 v[2];
    v[0] = *(const float4*)(row + t * 4);
    v[1] = *(const float4*)(row + 1024 + t * 4);
    float mx = fmaxf(fmaxf(v[0].x, v[0].y), fmaxf(v[0].z, v[0].w));
    mx = fmaxf(mx, fmaxf(fmaxf(v[1].x, v[1].y), fmaxf(v[1].z, v[1].w)));
    #pragma unroll
    for (int o = 16; o > 0; o >>= 1)
        mx = fmaxf(mx, __shfl_xor_sync(0xffffffffu, mx, o));
    if ((t & 31) == 0) sred[t >> 5] = mx;
    __syncthreads();
    mx = sred[0];
    #pragma unroll
    for (int w = 1; w < 8; w++) mx = fmaxf(mx, sred[w]);

    float s = 0.f;
    #pragma unroll
    for (int j = 0; j < 2; j++) {
        v[j].x = __expf(v[j].x - mx); v[j].y = __expf(v[j].y - mx);
        v[j].z = __expf(v[j].z - mx); v[j].w = __expf(v[j].w - mx);
        s += (v[j].x + v[j].y) + (v[j].z + v[j].w);
    }
    #pragma unroll
    for (int o = 16; o > 0; o >>= 1)
        s += __shfl_xor_sync(0xffffffffu, s, o);
    __syncthreads();
    if ((t & 31) == 0) sred[t >> 5] = s;
    __syncthreads();
    s = 0.f;
    #pragma unroll
    for (int w = 0; w < 8; w++) s += sred[w];

    const float inv = 1.f / s;
    #pragma unroll
    for (int j = 0; j < 2; j++) {
        v[j].x *= inv; v[j].y *= inv; v[j].z *= inv; v[j].w *= inv;
        *(float4*)(row + j * 1024 + t * 4) = v[j];
        __half2 h01 = __halves2half2(__float2half_rn(v[j].x), __float2half_rn(v[j].y));
        __half2 h23 = __halves2half2(__float2half_rn(v[j].z), __float2half_rn(v[j].w));
        *(__half2*)(sh + rbase + j * 1024 + t * 4)     = h01;
        *(__half2*)(sh + rbase + j * 1024 + t * 4 + 2) = h23;
    }
}

// ---------------------------------------------------------------------------
extern "C" void kernel_launch(void* const* d_in, const int* in_sizes, int n_in,
                              void* d_out, int out_size)
{
    (void)in_sizes; (void)n_in; (void)out_size;
    const float* q     = (const float*)d_in[0];   // [QL, B, DIM]
    const float* c     = (const float*)d_in[1];   // [CL, B, DIM]
    const float* W_in  = (const float*)d_in[2];   // [DIM, DIM]
    const float* W_out = (const float*)d_in[3];   // [DIM, 2*DIM]

    float* out   = (float*)d_out;                       // [QL, B, DIM]
    float* score = out + (size_t)QL * BATCH * DIM;      // [B, QL, CL]

    __half *qsph, *qspl, *csph, *cspl, *ctsph;
    __half *wisph, *wispl, *wosph;
    __half *qbsph, *qbspl, *ssph, *ctxsph;
    cudaGetSymbolAddress((void**)&qsph,  g_qsph);  cudaGetSymbolAddress((void**)&qspl,  g_qspl);
    cudaGetSymbolAddress((void**)&csph,  g_csph);  cudaGetSymbolAddress((void**)&cspl,  g_cspl);
    cudaGetSymbolAddress((void**)&ctsph, g_ctsph);
    cudaGetSymbolAddress((void**)&wisph, g_wisph); cudaGetSymbolAddress((void**)&wispl, g_wispl);
    cudaGetSymbolAddress((void**)&wosph, g_wosph);
    cudaGetSymbolAddress((void**)&qbsph, g_qbsph); cudaGetSymbolAddress((void**)&qbspl, g_qbspl);
    cudaGetSymbolAddress((void**)&ssph,  g_ssph);
    cudaGetSymbolAddress((void**)&ctxsph, g_ctxsph);

    cudaFuncSetAttribute(gemm_h3_kernel<2, 2, 0, false>, cudaFuncAttributeMaxDynamicSharedMemorySize, GEMM_SMEM);
    cudaFuncSetAttribute(gemm_h3_kernel<2, 2, 1, false>, cudaFuncAttributeMaxDynamicSharedMemorySize, GEMM_SMEM);
    cudaFuncSetAttribute(gemm_h3_kernel<1, 1, 3, false>, cudaFuncAttributeMaxDynamicSharedMemorySize, GEMM_SMEM);
    cudaFuncSetAttribute(gemm_h3_kernel<1, 1, 2, true >, cudaFuncAttributeMaxDynamicSharedMemorySize, GEMM_SMEM);

    const long sQB = (long)QL * DIM;       // per-batch strides
    const long sSC = (long)QL * CL;

    // -- pre-split passes (fp16 planes) --
    split_swap_h_kernel<<<dim3(QL, BATCH), 256>>>(q, qsph, qspl, BATCH, DIM);
    split_swap_h_kernel<<<dim3(DIM, 1), 256>>>(W_in,  wisph, wispl, 1, DIM);
    split_swap_h_kernel<<<dim3(DIM, 1), 256>>>(W_out, wosph, nullptr, 1, 2 * DIM);
    split_c_fused_kernel<<<dim3(CL / 32, DIM / 32, BATCH), 256>>>(c, csph, cspl, ctsph);

    // -- stage 1: qb = q . W_in^T  (2x2 planes, split fp16 out) --
    gemm_h3_kernel<2, 2, 0, false><<<dim3(DIM / BN, QL / BM, BATCH), 256, GEMM_SMEM>>>(
        qsph, qspl, nullptr, nullptr, sQB, DIM,
        wisph, wispl, 0, DIM,
        qbsph, qbspl, sQB, DIM,
        DIM, 0);

    // -- stage 2: score = qb . c^T  (2x2 planes, fp32 into output region) --
    gemm_h3_kernel<2, 2, 1, false><<<dim3(CL / BN, QL / BM, BATCH), 256, GEMM_SMEM>>>(
        qbsph, qbspl, nullptr, nullptr, sQB, DIM,
        csph, cspl, (long)CL * DIM, DIM,
        score, nullptr, sSC, CL,
        DIM, 0);

    // -- stage 3: softmax (fp32 in place + hi plane) --
    softmax_split_kernel<<<BATCH * QL, 256>>>(score, ssph);

    // -- stage 4: ctx = P . c  (1x1 planes; hi fp16 out only) --
    gemm_h3_kernel<1, 1, 3, false><<<dim3(DIM / BN, QL / BM, BATCH), 256, GEMM_SMEM>>>(
        ssph, nullptr, nullptr, nullptr, sSC, CL,
        ctsph, nullptr, (long)DIM * CL, CL,
        ctxsph, nullptr, sQB, DIM,
        CL, 0);

    // -- stage 5: out = tanh([ctx|qb] . W_out^T)  (1x1 planes, fp32 strided) --
    gemm_h3_kernel<1, 1, 2, true><<<dim3(DIM / BN, QL / BM, BATCH), 256, GEMM_SMEM>>>(
        ctxsph, nullptr, qbsph, nullptr, sQB, DIM,
        wosph, nullptr, 0, 2 * DIM,
        out, nullptr, DIM, (long)BATCH * DIM,
        2 * DIM, DIM);
}

// round 16
// speedup vs baseline: 1.6363x; 1.0648x over previous
#include <cuda_runtime.h>
#include <cuda_fp16.h>
#include <cstdint>
#include <math.h>

// Shapes (fixed)
#define QL 1024
#define CL 2048
#define BATCH 16
#define DIM 1024

// GEMM tiling: 128x64 block tile, BK=32 (two k16 substeps), 256 threads
#define BM 128
#define BN 64
#define NSTG 3

// smem sizes per instantiation (host-side mirror of in-kernel constants)
#define SMEM_22 (NSTG * (2 * 128 * 20 + 2 * 64 * 20) * 4)   // 92160 B
#define SMEM_11 (NSTG * (2 * 128 * 12 + 2 * 64 * 12) * 4)   // 55296 B

// ---------------------------------------------------------------------------
// Split-plane scratch (fp16 hi/lo; lo pre-scaled by 2048)
// ---------------------------------------------------------------------------
__device__ __half g_qsph [(size_t)BATCH * QL * DIM];
__device__ __half g_qspl [(size_t)BATCH * QL * DIM];
__device__ __half g_csph [(size_t)BATCH * CL * DIM];
__device__ __half g_cspl [(size_t)BATCH * CL * DIM];
__device__ __half g_ctsph[(size_t)BATCH * DIM * CL];   // ct hi (stage 4 B)
__device__ __half g_wisph[(size_t)DIM * DIM];
__device__ __half g_wispl[(size_t)DIM * DIM];
__device__ __half g_wosph[(size_t)DIM * 2 * DIM];      // W_out hi (stage 5 B)
__device__ __half g_qbsph[(size_t)BATCH * QL * DIM];
__device__ __half g_qbspl[(size_t)BATCH * QL * DIM];
__device__ __half g_ssph [(size_t)BATCH * QL * CL];    // P hi (stage 4 A)
__device__ __half g_ctxsph[(size_t)BATCH * QL * DIM];  // ctx hi (stage 5 A)

// ---------------------------------------------------------------------------
// helpers
// ---------------------------------------------------------------------------
__device__ __forceinline__ void cp16(uint32_t dst, const void* src) {
    asm volatile("cp.async.cg.shared.global [%0], [%1], 16;" :: "r"(dst), "l"(src));
}
__device__ __forceinline__ void cp_commit() { asm volatile("cp.async.commit_group;" ::: "memory"); }
__device__ __forceinline__ void cp_wait1()  { asm volatile("cp.async.wait_group 1;"  ::: "memory"); }

__device__ __forceinline__ void mma16(float* d, const uint32_t* a, const uint32_t* b) {
    asm volatile(
        "mma.sync.aligned.m16n8k16.row.col.f32.f16.f16.f32 "
        "{%0,%1,%2,%3}, {%4,%5,%6,%7}, {%8,%9}, {%0,%1,%2,%3};"
        : "+f"(d[0]), "+f"(d[1]), "+f"(d[2]), "+f"(d[3])
        : "r"(a[0]), "r"(a[1]), "r"(a[2]), "r"(a[3]), "r"(b[0]), "r"(b[1]));
}

__device__ __forceinline__ void ldmx4(uint32_t* r, uint32_t a) {
    asm volatile("ldmatrix.sync.aligned.m8n8.x4.shared.b16 {%0,%1,%2,%3}, [%4];"
        : "=r"(r[0]), "=r"(r[1]), "=r"(r[2]), "=r"(r[3]) : "r"(a));
}
__device__ __forceinline__ void ldmx2(uint32_t* r, uint32_t a) {
    asm volatile("ldmatrix.sync.aligned.m8n8.x2.shared.b16 {%0,%1}, [%2];"
        : "=r"(r[0]), "=r"(r[1]) : "r"(a));
}

// fp16 split: hi = rn_fp16(f); lo = rn_fp16((f - hi) * 2048)   (lo pre-scaled)
__device__ __forceinline__ void splith(float f, __half& h, __half& l) {
    h = __float2half_rn(f);
    l = __float2half_rn((f - __half2float(h)) * 2048.0f);
}

// fast tanh: 1 - 2/(1 + e^{2x}); saturates correctly.
__device__ __forceinline__ float fast_tanh(float x) {
    return 1.0f - 2.0f / (1.0f + __expf(2.0f * x));
}

// ---------------------------------------------------------------------------
// C[m][n] = sum_k A[m][k]*B[n][k], fp32 result via fp16 planes.
//   AT/BT in {1,2}: planes per operand.  D = Ah*Bh (+Al*Bh) (+Ah*Bl);
//   lo planes pre-scaled by 2048, recombined as accH + accL/2048.
// MODE 0: split planes out (Cv=hi, Cv2=lo) | 1: fp32 | 2: tanh fp32 | 3: hi fp16
// Smem layout derived from AT/BT: row stride PA/PB = 20 b32 (2-plane: 16 data
// + 4 pad) or 12 b32 (1-plane: 8 data + 4 pad). Both strides give
// conflict-free 8-phase ldmatrix banks (20r / 12r mod 32 distinct, 16B
// aligned). 1-plane variant: 55.3KB smem, 3 CTAs/SM.
// ---------------------------------------------------------------------------
template<int AT, int BT, int MODE, bool CONCAT>
__global__ __launch_bounds__(256, (AT == 1 && BT == 1) ? 3 : 2)
void gemm_h3_kernel(const __half* __restrict__ Ah, const __half* __restrict__ Al,
                    const __half* __restrict__ A1h, const __half* __restrict__ A1l,
                    long Abs, long lda,
                    const __half* __restrict__ Bh, const __half* __restrict__ Bl,
                    long Bbs, long ldb,
                    void* __restrict__ Cv, void* __restrict__ Cv2,
                    long Cbs, long ldc,
                    int K, int Ksplit)
{
    constexpr int PA = (AT == 2) ? 20 : 12;     // A row stride (b32)
    constexpr int PB = (BT == 2) ? 20 : 12;     // B row stride (b32)
    constexpr int A_SUBT = 128 * PA;            // b32 per k16 A subtile
    constexpr int B_SUBT = 64 * PB;
    constexpr int STGT = 2 * A_SUBT + 2 * B_SUBT;
    constexpr int NTASK = 512 * AT + 256 * BT;  // 16B copy tasks per k32 chunk
    constexpr int NIT = NTASK / 256;

    extern __shared__ uint32_t smem32[];
    const uint32_t smem_addr = (uint32_t)__cvta_generic_to_shared(smem32);

    const int bi = blockIdx.z;
    const int m0 = blockIdx.y * BM;
    const int n0 = blockIdx.x * BN;
    const int tid  = threadIdx.x;
    const int lane = tid & 31;
    const int wid  = tid >> 5;
    const int wm = (wid & 3) * 32;     // warp m offset
    const int wn = (wid >> 2) * 32;    // warp n offset
    const int g  = lane >> 2;
    const int t  = lane & 3;

    const bool useL = (AT == 2) || (BT == 2);

    const __half* A0h_b = Ah + (long)bi * Abs;
    const __half* A0l_b = (AT == 2) ? (Al + (long)bi * Abs) : A0h_b;
    const __half* A1h_b = CONCAT ? (A1h + (long)bi * Abs) : A0h_b;
    const __half* A1l_b = (CONCAT && AT == 2) ? (A1l + (long)bi * Abs) : A1h_b;
    const __half* Bh_b  = Bh + (long)bi * Bbs;
    const __half* Bl_b  = (BT == 2) ? (Bl + (long)bi * Bbs) : Bh_b;

    // ldmatrix per-lane byte offsets (within a k16 subtile region)
    const int laA = lane & 15, sgA = lane >> 4;
    uint32_t offA[2];
    #pragma unroll
    for (int i = 0; i < 2; i++)
        offA[i] = (uint32_t)(((wm + i * 16 + laA) * PA + sgA * 4) * 4);
    const int laB = lane & 7, sgB = (lane >> 3) & 1;
    uint32_t offB[4];
    #pragma unroll
    for (int j = 0; j < 4; j++)
        offB[j] = (uint32_t)(((wn + j * 8 + laB) * PB + sgB * 4) * 4);

    float accH[2][4][4], accL[2][4][4];
    #pragma unroll
    for (int i = 0; i < 2; i++)
        #pragma unroll
        for (int j = 0; j < 4; j++)
            #pragma unroll
            for (int r = 0; r < 4; r++) { accH[i][j][r] = 0.f; accL[i][j][r] = 0.f; }

    const int niter = K / 32;

    // Task layout: [0, 512*AT): A (hi plane first 512, lo next 512)
    //              [512*AT, +256*BT): B (hi first 256, lo next 256)
    auto prefetch = [&](int it, int buf) {
        const int k0 = it * 32;
        const __half *pAh, *pAl; int ka;
        if (CONCAT && k0 >= Ksplit) { pAh = A1h_b; pAl = A1l_b; ka = k0 - Ksplit; }
        else                        { pAh = A0h_b; pAl = A0l_b; ka = k0; }
        const uint32_t sb32 = (uint32_t)buf * STGT;
        #pragma unroll
        for (int j = 0; j < NIT; ++j) {
            const int task = tid + j * 256;
            uint32_t dst32; const __half* src;
            if (task < 512 * AT) {                     // A tasks
                const int plane = (AT == 2) ? (task >> 9) : 0;
                const int idx = task & 511;            // subk(1) row(7) h16(1)
                const int subk = idx >> 8;
                const int row = (idx >> 1) & 127;
                const int h16 = idx & 1;
                dst32 = sb32 + (uint32_t)subk * A_SUBT + (uint32_t)row * PA
                        + (uint32_t)plane * 8 + (uint32_t)h16 * 4;
                src = (plane ? pAl : pAh) + (long)(m0 + row) * lda + ka + subk * 16 + h16 * 8;
            } else {                                   // B tasks
                const int bt = task - 512 * AT;
                const int plane = (BT == 2) ? (bt >> 8) : 0;
                const int idx = bt & 255;              // subk(1) row(6) h16(1)
                const int subk = idx >> 7;
                const int row = (idx >> 1) & 63;
                const int h16 = idx & 1;
                dst32 = sb32 + 2 * A_SUBT + (uint32_t)subk * B_SUBT + (uint32_t)row * PB
                        + (uint32_t)plane * 8 + (uint32_t)h16 * 4;
                src = (plane ? Bl_b : Bh_b) + (long)(n0 + row) * ldb + k0 + subk * 16 + h16 * 8;
            }
            cp16(smem_addr + dst32 * 4, src);
        }
    };

    prefetch(0, 0);
    cp_commit();
    if (niter > 1) prefetch(1, 1);
    cp_commit();

    for (int it = 0; it < niter; it++) {
        const int buf = it % NSTG;
        cp_wait1();
        __syncthreads();
        // Single barrier per chunk: orders all warps' compute of it-1 before
        // prefetch into buffer (it+2)%3 == (it-1)%3.
        if (it + 2 < niter) prefetch(it + 2, (it + 2) % NSTG);
        cp_commit();

        const uint32_t sb32 = (uint32_t)buf * STGT;
        #pragma unroll
        for (int s = 0; s < 2; ++s) {                 // two k16 substeps
            const uint32_t subA = smem_addr + (sb32 + (uint32_t)s * A_SUBT) * 4;
            const uint32_t subB = smem_addr + (sb32 + 2 * A_SUBT + (uint32_t)s * B_SUBT) * 4;

            uint32_t ah[2][4], al[2][4], bh[4][2], bl[4][2];
            ldmx4(ah[0], subA + offA[0]);
            ldmx4(ah[1], subA + offA[1]);
            if (AT == 2) {
                ldmx4(al[0], subA + offA[0] + 32);    // lo plane at +8 b32
                ldmx4(al[1], subA + offA[1] + 32);
            }
            #pragma unroll
            for (int j = 0; j < 4; j++) {
                ldmx2(bh[j], subB + offB[j]);
                if (BT == 2) ldmx2(bl[j], subB + offB[j] + 32);
            }
            // term-outer: each group of 8 MMAs mutually independent
            #pragma unroll
            for (int i = 0; i < 2; i++)
                #pragma unroll
                for (int j = 0; j < 4; j++)
                    mma16(accH[i][j], ah[i], bh[j]);
            if (AT == 2)
                #pragma unroll
                for (int i = 0; i < 2; i++)
                    #pragma unroll
                    for (int j = 0; j < 4; j++)
                        mma16(accL[i][j], al[i], bh[j]);
            if (BT == 2)
                #pragma unroll
                for (int i = 0; i < 2; i++)
                    #pragma unroll
                    for (int j = 0; j < 4; j++)
                        mma16(accL[i][j], ah[i], bl[j]);
        }
    }

    // epilogue: c0(g,2t) c1(g,2t+1) c2(g+8,2t) c3(g+8,2t+1)
    const float inv2048 = 1.0f / 2048.0f;
    #pragma unroll
    for (int i = 0; i < 2; i++) {
        const int r0 = m0 + wm + i * 16 + g;
        #pragma unroll
        for (int j = 0; j < 4; j++) {
            const int cc = n0 + wn + j * 8 + t * 2;
            float v0 = accH[i][j][0], v1 = accH[i][j][1];
            float v2 = accH[i][j][2], v3 = accH[i][j][3];
            if (useL) {
                v0 += accL[i][j][0] * inv2048;
                v1 += accL[i][j][1] * inv2048;
                v2 += accL[i][j][2] * inv2048;
                v3 += accL[i][j][3] * inv2048;
            }
            if (MODE == 0) {
                __half* Ch = (__half*)Cv  + (long)bi * Cbs;
                __half* Cl = (__half*)Cv2 + (long)bi * Cbs;
                __half h0, l0, h1, l1;
                splith(v0, h0, l0); splith(v1, h1, l1);
                *(__half2*)&Ch[(long)r0 * ldc + cc] = __halves2half2(h0, h1);
                *(__half2*)&Cl[(long)r0 * ldc + cc] = __halves2half2(l0, l1);
                splith(v2, h0, l0); splith(v3, h1, l1);
                *(__half2*)&Ch[(long)(r0 + 8) * ldc + cc] = __halves2half2(h0, h1);
                *(__half2*)&Cl[(long)(r0 + 8) * ldc + cc] = __halves2half2(l0, l1);
            } else if (MODE == 3) {
                __half* Ch = (__half*)Cv + (long)bi * Cbs;
                *(__half2*)&Ch[(long)r0 * ldc + cc] =
                    __halves2half2(__float2half_rn(v0), __float2half_rn(v1));
                *(__half2*)&Ch[(long)(r0 + 8) * ldc + cc] =
                    __halves2half2(__float2half_rn(v2), __float2half_rn(v3));
            } else {
                float* Cp = (float*)Cv + (long)bi * Cbs;
                if (MODE == 2) {
                    v0 = fast_tanh(v0); v1 = fast_tanh(v1);
                    v2 = fast_tanh(v2); v3 = fast_tanh(v3);
                }
                *(float2*)&Cp[(long)r0 * ldc + cc]       = make_float2(v0, v1);
                *(float2*)&Cp[(long)(r0 + 8) * ldc + cc] = make_float2(v2, v3);
            }
        }
    }
}

// ---------------------------------------------------------------------------
// in[r0, r1, L] fp32 -> hi/lo fp16 planes at [(r1*R0 + r0)*L]  (dim swap+split)
// ---------------------------------------------------------------------------
__global__ __launch_bounds__(256)
void split_swap_h_kernel(const float* __restrict__ in,
                         __half* __restrict__ oh, __half* __restrict__ ol,
                         int R1, int L)
{
    const long r0 = blockIdx.x, r1 = blockIdx.y;
    const float* src = in + (r0 * R1 + r1) * (long)L;
    const long dbase = (r1 * gridDim.x + r0) * (long)L;
    for (int i = threadIdx.x * 4; i < L; i += blockDim.x * 4) {
        float4 v = *(const float4*)(src + i);
        __half h0, l0, h1, l1, h2, l2, h3, l3;
        splith(v.x, h0, l0); splith(v.y, h1, l1);
        splith(v.z, h2, l2); splith(v.w, h3, l3);
        *(__half2*)&oh[dbase + i]     = __halves2half2(h0, h1);
        *(__half2*)&oh[dbase + i + 2] = __halves2half2(h2, h3);
        if (ol) {
            *(__half2*)&ol[dbase + i]     = __halves2half2(l0, l1);
            *(__half2*)&ol[dbase + i + 2] = __halves2half2(l2, l3);
        }
    }
}

// ---------------------------------------------------------------------------
// Fused c pre-pass: one read of c[CL, B, DIM] produces
//   csph/cspl [B, CL, DIM]  (dim-swap + hi/lo split, stage 2 B)
//   ctsph     [B, DIM, CL]  (transpose hi plane, stage 4 B)
// ---------------------------------------------------------------------------
__global__ __launch_bounds__(256)
void split_c_fused_kernel(const float* __restrict__ c,
                          __half* __restrict__ csh, __half* __restrict__ csl,
                          __half* __restrict__ cth)
{
    __shared__ float tile[32][33];
    const int b  = blockIdx.z;
    const int k0 = blockIdx.x * 32;
    const int d0 = blockIdx.y * 32;
    const int tx = threadIdx.x & 31;
    const int ty = threadIdx.x >> 5;

    #pragma unroll
    for (int r = 0; r < 32; r += 8) {
        float f = c[(long)(k0 + ty + r) * (BATCH * DIM) + (long)b * DIM + d0 + tx];
        tile[ty + r][tx] = f;
        __half h, l;
        splith(f, h, l);
        long idx = ((long)b * CL + k0 + ty + r) * DIM + d0 + tx;   // [B, CL, DIM]
        csh[idx] = h;
        csl[idx] = l;
    }
    __syncthreads();
    #pragma unroll
    for (int r = 0; r < 32; r += 8) {
        long idx = ((long)b * DIM + d0 + ty + r) * CL + k0 + tx;   // [B, DIM, CL]
        cth[idx] = __float2half_rn(tile[tx][ty + r]);
    }
}

// ---------------------------------------------------------------------------
// softmax over rows of 2048: fp32 probs in place + hi fp16 plane (float4 I/O)
// ---------------------------------------------------------------------------
__global__ __launch_bounds__(256)
void softmax_split_kernel(float* __restrict__ S, __half* __restrict__ sh)
{
    const long rbase = (long)blockIdx.x * 2048;
    float* row = S + rbase;
    const int t = threadIdx.x;
    __shared__ float sred[8];

    float4 v[2];
    v[0] = *(const float4*)(row + t * 4);
    v[1] = *(const float4*)(row + 1024 + t * 4);
    float mx = fmaxf(fmaxf(v[0].x, v[0].y), fmaxf(v[0].z, v[0].w));
    mx = fmaxf(mx, fmaxf(fmaxf(v[1].x, v[1].y), fmaxf(v[1].z, v[1].w)));
    #pragma unroll
    for (int o = 16; o > 0; o >>= 1)
        mx = fmaxf(mx, __shfl_xor_sync(0xffffffffu, mx, o));
    if ((t & 31) == 0) sred[t >> 5] = mx;
    __syncthreads();
    mx = sred[0];
    #pragma unroll
    for (int w = 1; w < 8; w++) mx = fmaxf(mx, sred[w]);

    float s = 0.f;
    #pragma unroll
    for (int j = 0; j < 2; j++) {
        v[j].x = __expf(v[j].x - mx); v[j].y = __expf(v[j].y - mx);
        v[j].z = __expf(v[j].z - mx); v[j].w = __expf(v[j].w - mx);
        s += (v[j].x + v[j].y) + (v[j].z + v[j].w);
    }
    #pragma unroll
    for (int o = 16; o > 0; o >>= 1)
        s += __shfl_xor_sync(0xffffffffu, s, o);
    __syncthreads();
    if ((t & 31) == 0) sred[t >> 5] = s;
    __syncthreads();
    s = 0.f;
    #pragma unroll
    for (int w = 0; w < 8; w++) s += sred[w];

    const float inv = 1.f / s;
    #pragma unroll
    for (int j = 0; j < 2; j++) {
        v[j].x *= inv; v[j].y *= inv; v[j].z *= inv; v[j].w *= inv;
        *(float4*)(row + j * 1024 + t * 4) = v[j];
        __half2 h01 = __halves2half2(__float2half_rn(v[j].x), __float2half_rn(v[j].y));
        __half2 h23 = __halves2half2(__float2half_rn(v[j].z), __float2half_rn(v[j].w));
        *(__half2*)(sh + rbase + j * 1024 + t * 4)     = h01;
        *(__half2*)(sh + rbase + j * 1024 + t * 4 + 2) = h23;
    }
}

// ---------------------------------------------------------------------------
extern "C" void kernel_launch(void* const* d_in, const int* in_sizes, int n_in,
                              void* d_out, int out_size)
{
    (void)in_sizes; (void)n_in; (void)out_size;
    const float* q     = (const float*)d_in[0];   // [QL, B, DIM]
    const float* c     = (const float*)d_in[1];   // [CL, B, DIM]
    const float* W_in  = (const float*)d_in[2];   // [DIM, DIM]
    const float* W_out = (const float*)d_in[3];   // [DIM, 2*DIM]

    float* out   = (float*)d_out;                       // [QL, B, DIM]
    float* score = out + (size_t)QL * BATCH * DIM;      // [B, QL, CL]

    __half *qsph, *qspl, *csph, *cspl, *ctsph;
    __half *wisph, *wispl, *wosph;
    __half *qbsph, *qbspl, *ssph, *ctxsph;
    cudaGetSymbolAddress((void**)&qsph,  g_qsph);  cudaGetSymbolAddress((void**)&qspl,  g_qspl);
    cudaGetSymbolAddress((void**)&csph,  g_csph);  cudaGetSymbolAddress((void**)&cspl,  g_cspl);
    cudaGetSymbolAddress((void**)&ctsph, g_ctsph);
    cudaGetSymbolAddress((void**)&wisph, g_wisph); cudaGetSymbolAddress((void**)&wispl, g_wispl);
    cudaGetSymbolAddress((void**)&wosph, g_wosph);
    cudaGetSymbolAddress((void**)&qbsph, g_qbsph); cudaGetSymbolAddress((void**)&qbspl, g_qbspl);
    cudaGetSymbolAddress((void**)&ssph,  g_ssph);
    cudaGetSymbolAddress((void**)&ctxsph, g_ctxsph);

    cudaFuncSetAttribute(gemm_h3_kernel<2, 2, 0, false>, cudaFuncAttributeMaxDynamicSharedMemorySize, SMEM_22);
    cudaFuncSetAttribute(gemm_h3_kernel<2, 2, 1, false>, cudaFuncAttributeMaxDynamicSharedMemorySize, SMEM_22);
    cudaFuncSetAttribute(gemm_h3_kernel<1, 1, 3, false>, cudaFuncAttributeMaxDynamicSharedMemorySize, SMEM_11);
    cudaFuncSetAttribute(gemm_h3_kernel<1, 1, 2, true >, cudaFuncAttributeMaxDynamicSharedMemorySize, SMEM_11);

    const long sQB = (long)QL * DIM;       // per-batch strides
    const long sSC = (long)QL * CL;

    // -- pre-split passes (fp16 planes) --
    split_swap_h_kernel<<<dim3(QL, BATCH), 256>>>(q, qsph, qspl, BATCH, DIM);
    split_swap_h_kernel<<<dim3(DIM, 1), 256>>>(W_in,  wisph, wispl, 1, DIM);
    split_swap_h_kernel<<<dim3(DIM, 1), 256>>>(W_out, wosph, nullptr, 1, 2 * DIM);
    split_c_fused_kernel<<<dim3(CL / 32, DIM / 32, BATCH), 256>>>(c, csph, cspl, ctsph);

    // -- stage 1: qb = q . W_in^T  (2x2 planes, split fp16 out) --
    gemm_h3_kernel<2, 2, 0, false><<<dim3(DIM / BN, QL / BM, BATCH), 256, SMEM_22>>>(
        qsph, qspl, nullptr, nullptr, sQB, DIM,
        wisph, wispl, 0, DIM,
        qbsph, qbspl, sQB, DIM,
        DIM, 0);

    // -- stage 2: score = qb . c^T  (2x2 planes, fp32 into output region) --
    gemm_h3_kernel<2, 2, 1, false><<<dim3(CL / BN, QL / BM, BATCH), 256, SMEM_22>>>(
        qbsph, qbspl, nullptr, nullptr, sQB, DIM,
        csph, cspl, (long)CL * DIM, DIM,
        score, nullptr, sSC, CL,
        DIM, 0);

    // -- stage 3: softmax (fp32 in place + hi plane) --
    softmax_split_kernel<<<BATCH * QL, 256>>>(score, ssph);

    // -- stage 4: ctx = P . c  (1x1 planes, compact smem, occ 3) --
    gemm_h3_kernel<1, 1, 3, false><<<dim3(DIM / BN, QL / BM, BATCH), 256, SMEM_11>>>(
        ssph, nullptr, nullptr, nullptr, sSC, CL,
        ctsph, nullptr, (long)DIM * CL, CL,
        ctxsph, nullptr, sQB, DIM,
        CL, 0);

    // -- stage 5: out = tanh([ctx|qb] . W_out^T)  (1x1 planes, occ 3) --
    gemm_h3_kernel<1, 1, 2, true><<<dim3(DIM / BN, QL / BM, BATCH), 256, SMEM_11>>>(
        ctxsph, nullptr, qbsph, nullptr, sQB, DIM,
        wosph, nullptr, 0, 2 * DIM,
        out, nullptr, DIM, (long)BATCH * DIM,
        2 * DIM, DIM);
}